// round 5
// baseline (speedup 1.0000x reference)
#include <cuda_runtime.h>
#include <cuda_bf16.h>
#include <cstdint>

#define BB 2
#define CC 128
#define NN 4096
#define THRESH2 64.0f
#define BN_EPS 1e-5f

// ---------------- scratch (device globals) -----------------------------------
__device__ __nv_bfloat16 g_xb[BB * NN * CC];          // hi split, 2 MB
__device__ __nv_bfloat16 g_xl[BB * NN * CC];          // lo split, 2 MB
__device__ __nv_bfloat16 g_Whi[CC * CC];
__device__ __nv_bfloat16 g_Wlo[CC * CC];
__device__ float g_sq[BB * NN];
__device__ float g_y [BB * NN * CC];
__device__ unsigned int g_Hb[(size_t)BB * NN * (NN / 32)];  // bit mask, 4 MB
__device__ float g_E [BB * NN * CC];
__device__ float g_xe[BB * NN * CC];
__device__ float g_part2[512][2][CC];                 // per-agg1-block stats partials
__device__ float g_mean[CC];
__device__ float g_rstd[CC];

__device__ __forceinline__ uint32_t smem_u32(const void* p) {
    uint32_t a;
    asm("{ .reg .u64 t; cvta.to.shared.u64 t, %1; cvt.u32.u64 %0, t; }" : "=r"(a) : "l"(p));
    return a;
}
__device__ __forceinline__ void ldm_x4(uint32_t a[4], uint32_t addr) {
    asm volatile("ldmatrix.sync.aligned.m8n8.x4.shared.b16 {%0,%1,%2,%3}, [%4];"
                 : "=r"(a[0]), "=r"(a[1]), "=r"(a[2]), "=r"(a[3]) : "r"(addr));
}
__device__ __forceinline__ void mma16816(float c[4], const uint32_t a[4], const uint32_t b[2]) {
    asm volatile(
        "mma.sync.aligned.m16n8k16.row.col.f32.bf16.bf16.f32 "
        "{%0,%1,%2,%3}, {%4,%5,%6,%7}, {%8,%9}, {%0,%1,%2,%3};"
        : "+f"(c[0]), "+f"(c[1]), "+f"(c[2]), "+f"(c[3])
        : "r"(a[0]), "r"(a[1]), "r"(a[2]), "r"(a[3]), "r"(b[0]), "r"(b[1]));
}

// ---------------- K0: W hi/lo split ------------------------------------------
__global__ void wprep_kernel(const float* __restrict__ Wfc) {
    int i = blockIdx.x * blockDim.x + threadIdx.x;
    float v = Wfc[i];
    __nv_bfloat16 h = __float2bfloat16(v);
    g_Whi[i] = h;
    g_Wlo[i] = __float2bfloat16(v - __bfloat162float(h));
}

// ---------------- K1: NCHW -> [b][n][c] hi/lo split + row sq (no atomics) ----
// block (32,8), grid (NN/32, BB). Block owns 32 n-rows across ALL channels.
__global__ void transpose_kernel(const float* __restrict__ x) {
    __shared__ float tile[32][33];
    int b = blockIdx.y;
    int n0 = blockIdx.x * 32;
    int tx = threadIdx.x, ty = threadIdx.y;
    float sq_acc[4] = {0.f, 0.f, 0.f, 0.f};

    for (int ct = 0; ct < 4; ct++) {
        int c0 = ct * 32;
        if (ct) __syncthreads();
        #pragma unroll
        for (int r = 0; r < 32; r += 8)
            tile[ty + r][tx] = x[((size_t)b * CC + c0 + ty + r) * NN + n0 + tx];
        __syncthreads();
        #pragma unroll
        for (int rr = 0; rr < 4; rr++) {
            int r = rr * 8;
            float v = tile[tx][ty + r];
            size_t o = ((size_t)b * NN + n0 + ty + r) * CC + c0 + tx;
            __nv_bfloat16 h = __float2bfloat16(v);
            g_xb[o] = h;
            g_xl[o] = __float2bfloat16(v - __bfloat162float(h));
            float s = v * v;
            #pragma unroll
            for (int o2 = 16; o2 > 0; o2 >>= 1) s += __shfl_xor_sync(0xffffffffu, s, o2);
            sq_acc[rr] += s;
        }
    }
    if (tx == 0) {
        #pragma unroll
        for (int rr = 0; rr < 4; rr++)
            g_sq[(size_t)b * NN + n0 + ty + rr * 8] = sq_acc[rr];
    }
}

// ---------------- K2: y = xf @ W^T + b  (split-bf16 HMMA, 64-row tiles) ------
#define YS_AH 0
#define YS_AL 16384
#define YS_WH 32768
#define YS_WL 65536
#define YS_TOTAL 98304

__global__ void __launch_bounds__(256, 2) gemm_y_mma(const float* __restrict__ bfc) {
    extern __shared__ char smem[];
    int tid = threadIdx.x;
    int wid = tid >> 5, lane = tid & 31;
    int b = blockIdx.y;
    int n0 = blockIdx.x * 64;

    {
        const uint4* Ah = (const uint4*)(g_xb + ((size_t)b * NN + n0) * CC);
        const uint4* Al = (const uint4*)(g_xl + ((size_t)b * NN + n0) * CC);
        #pragma unroll
        for (int it = 0; it < 4; it++) {
            int id = tid + it * 256;                   // 0..1023 (64 rows x 16 ch)
            int row = id >> 4, ch = id & 15;
            int off = row * 256 + (ch ^ (row & 7)) * 16;
            *(uint4*)(smem + YS_AH + off) = Ah[(size_t)row * 16 + ch];
            *(uint4*)(smem + YS_AL + off) = Al[(size_t)row * 16 + ch];
        }
        const uint4* Wh = (const uint4*)g_Whi;
        const uint4* Wl = (const uint4*)g_Wlo;
        #pragma unroll
        for (int it = 0; it < 8; it++) {
            int id = tid + it * 256;                   // 0..2047
            int row = id >> 4, ch = id & 15;
            int off = row * 256 + (ch ^ (row & 7)) * 16;
            *(uint4*)(smem + YS_WH + off) = Wh[(size_t)row * 16 + ch];
            *(uint4*)(smem + YS_WL + off) = Wl[(size_t)row * 16 + ch];
        }
    }
    __syncthreads();

    int warp_m = wid & 1, warp_n = wid >> 1;           // 2 x 4 warps
    int mbase = warp_m * 32, nbase = warp_n * 32;

    float acc[2][4][4];
    #pragma unroll
    for (int mt = 0; mt < 2; mt++)
        #pragma unroll
        for (int nt = 0; nt < 4; nt++)
            #pragma unroll
            for (int q = 0; q < 4; q++) acc[mt][nt][q] = 0.f;

    int a_row_local = lane & 15;
    int a_hi = lane >> 4;
    int bg = lane >> 3;
    int b_row_local = lane & 7;
    int b_nt_off = bg >> 1;
    int b_hi = bg & 1;

    #pragma unroll
    for (int pass = 0; pass < 3; pass++) {
        uint32_t Abase = smem_u32(smem + (pass == 2 ? YS_AL : YS_AH));
        uint32_t Bbase = smem_u32(smem + (pass == 1 ? YS_WL : YS_WH));
        #pragma unroll
        for (int kk = 0; kk < 8; kk++) {
            uint32_t afr[2][4];
            #pragma unroll
            for (int mt = 0; mt < 2; mt++) {
                int row = mbase + mt * 16 + a_row_local;
                int ch = (2 * kk + a_hi) ^ (row & 7);
                ldm_x4(afr[mt], Abase + row * 256 + ch * 16);
            }
            uint32_t bfr[4][2];
            #pragma unroll
            for (int nt2 = 0; nt2 < 2; nt2++) {
                int row = nbase + nt2 * 16 + b_nt_off * 8 + b_row_local;
                int ch = (2 * kk + b_hi) ^ (row & 7);
                uint32_t r4[4];
                ldm_x4(r4, Bbase + row * 256 + ch * 16);
                bfr[nt2 * 2][0] = r4[0]; bfr[nt2 * 2][1] = r4[1];
                bfr[nt2 * 2 + 1][0] = r4[2]; bfr[nt2 * 2 + 1][1] = r4[3];
            }
            #pragma unroll
            for (int mt = 0; mt < 2; mt++)
                #pragma unroll
                for (int nt = 0; nt < 4; nt++)
                    mma16816(acc[mt][nt], afr[mt], bfr[nt]);
        }
    }

    int rrow = lane >> 2;
    int ccol = (lane & 3) * 2;
    float* Y = g_y + ((size_t)b * NN + n0) * CC;
    #pragma unroll
    for (int mt = 0; mt < 2; mt++) {
        #pragma unroll
        for (int nt = 0; nt < 4; nt++) {
            int col = nbase + nt * 8 + ccol;
            float b0 = bfc[col], b1 = bfc[col + 1];
            #pragma unroll
            for (int h = 0; h < 2; h++) {
                int row = mbase + mt * 16 + rrow + h * 8;
                Y[(size_t)row * CC + col]     = acc[mt][nt][h * 2 + 0] + b0;
                Y[(size_t)row * CC + col + 1] = acc[mt][nt][h * 2 + 1] + b1;
            }
        }
    }
}

// ---------------- K3: HMMA Gram + threshold -> bit mask (unchanged core) -----
#define HS_SQI 0
#define HS_SQJ 512
#define HS_A   1024
#define HS_B   33792
#define HS_H   66560
#define SH_STRIDE 144
#define HS_TOTAL (66560 + 128 * SH_STRIDE)

__global__ void __launch_bounds__(256, 2) gemm_H_mma() {
    extern __shared__ char smem[];
    int tid = threadIdx.x;
    int wid = tid >> 5, lane = tid & 31;
    int b = blockIdx.y;

    int idx = blockIdx.x, ti = 0, rem = 32;
    while (idx >= rem) { idx -= rem; ti++; rem--; }
    int tj = ti + idx;
    int n0 = ti * 128, m0 = tj * 128;

    float* sSqI = (float*)(smem + HS_SQI);
    float* sSqJ = (float*)(smem + HS_SQJ);
    if (tid < 128) {
        sSqI[tid] = g_sq[(size_t)b * NN + n0 + tid];
        sSqJ[tid] = g_sq[(size_t)b * NN + m0 + tid];
    }

    {
        const uint4* Ag = (const uint4*)(g_xb + ((size_t)b * NN + n0) * CC);
        const uint4* Bg = (const uint4*)(g_xb + ((size_t)b * NN + m0) * CC);
        #pragma unroll
        for (int it = 0; it < 8; it++) {
            int id = tid + it * 256;
            int row = id >> 4, ch = id & 15;
            int off = row * 256 + (ch ^ (row & 7)) * 16;
            *(uint4*)(smem + HS_A + off) = Ag[(size_t)row * 16 + ch];
            *(uint4*)(smem + HS_B + off) = Bg[(size_t)row * 16 + ch];
        }
    }
    __syncthreads();

    int warp_m = wid & 3, warp_n = wid >> 2;
    int mbase = warp_m * 32, nbase = warp_n * 64;

    float acc[2][8][4];
    #pragma unroll
    for (int mt = 0; mt < 2; mt++)
        #pragma unroll
        for (int nt = 0; nt < 8; nt++)
            #pragma unroll
            for (int q = 0; q < 4; q++) acc[mt][nt][q] = 0.f;

    uint32_t Abase = smem_u32(smem + HS_A);
    uint32_t Bbase = smem_u32(smem + HS_B);

    int a_row_local = lane & 15;
    int a_hi = lane >> 4;
    int bg = lane >> 3;
    int b_row_local = lane & 7;
    int b_nt_off = bg >> 1;
    int b_hi = bg & 1;

    #pragma unroll
    for (int kk = 0; kk < 8; kk++) {
        uint32_t afr[2][4];
        #pragma unroll
        for (int mt = 0; mt < 2; mt++) {
            int row = mbase + mt * 16 + a_row_local;
            int ch = (2 * kk + a_hi) ^ (row & 7);
            ldm_x4(afr[mt], Abase + row * 256 + ch * 16);
        }
        uint32_t bfr[8][2];
        #pragma unroll
        for (int nt2 = 0; nt2 < 4; nt2++) {
            int row = nbase + nt2 * 16 + b_nt_off * 8 + b_row_local;
            int ch = (2 * kk + b_hi) ^ (row & 7);
            uint32_t r4[4];
            ldm_x4(r4, Bbase + row * 256 + ch * 16);
            bfr[nt2 * 2][0] = r4[0]; bfr[nt2 * 2][1] = r4[1];
            bfr[nt2 * 2 + 1][0] = r4[2]; bfr[nt2 * 2 + 1][1] = r4[3];
        }
        #pragma unroll
        for (int mt = 0; mt < 2; mt++)
            #pragma unroll
            for (int nt = 0; nt < 8; nt++)
                mma16816(acc[mt][nt], afr[mt], bfr[nt]);
    }

    unsigned char* sH = (unsigned char*)(smem + HS_H);
    int rrow = lane >> 2;
    int ccol = (lane & 3) * 2;
    #pragma unroll
    for (int mt = 0; mt < 2; mt++) {
        #pragma unroll
        for (int nt = 0; nt < 8; nt++) {
            int col = nbase + nt * 8 + ccol;
            float sm0 = sSqJ[col], sm1 = sSqJ[col + 1];
            #pragma unroll
            for (int h = 0; h < 2; h++) {
                int row = mbase + mt * 16 + rrow + h * 8;
                float sqn = sSqI[row];
                float d20 = sqn + sm0 - 2.0f * acc[mt][nt][h * 2 + 0];
                float d21 = sqn + sm1 - 2.0f * acc[mt][nt][h * 2 + 1];
                sH[row * SH_STRIDE + col]     = (d20 < THRESH2) ? 1 : 0;
                sH[row * SH_STRIDE + col + 1] = (d21 < THRESH2) ? 1 : 0;
            }
        }
    }
    __syncthreads();

    unsigned int* Hb = g_Hb + (size_t)b * NN * (NN / 32);
    #pragma unroll
    for (int it = 0; it < 2; it++) {
        int id = tid + it * 256;
        int row = id >> 2, w = id & 3;
        const unsigned int* src = (const unsigned int*)(sH + row * SH_STRIDE + w * 32);
        unsigned int bits = 0;
        #pragma unroll
        for (int k = 0; k < 8; k++) {
            unsigned int u = src[k];
            bits |= (u & 1u) << (k * 4);
            bits |= ((u >> 8) & 1u) << (k * 4 + 1);
            bits |= ((u >> 16) & 1u) << (k * 4 + 2);
            bits |= ((u >> 24) & 1u) << (k * 4 + 3);
        }
        Hb[(size_t)(n0 + row) * (NN / 32) + (m0 >> 5) + w] = bits;
    }
    if (ti != tj && tid < 128) {
        int mrow = tid;
        unsigned int wbits[4];
        #pragma unroll
        for (int w = 0; w < 4; w++) {
            unsigned int bits = 0;
            #pragma unroll
            for (int q = 0; q < 32; q++)
                bits |= (unsigned int)(sH[(w * 32 + q) * SH_STRIDE + mrow] & 1u) << q;
            wbits[w] = bits;
        }
        *(uint4*)&Hb[(size_t)(m0 + mrow) * (NN / 32) + (n0 >> 5)] =
            make_uint4(wbits[0], wbits[1], wbits[2], wbits[3]);
    }
}

// ---------------- K4/K5: aggregation via deterministic compaction ------------
// block 128 threads (t = channel AND word index), 16 rows per block.
// MODE 0: E = (H@y)/deg.  MODE 1: xe = y + (H@E)/deg, + per-block BN partials.
#define AGG_R 16
template <int MODE>
__global__ void __launch_bounds__(128) agg_kernel() {
    int b = blockIdx.y;
    int n0 = blockIdx.x * AGG_R;
    int t = threadIdx.x;
    int lane = t & 31, wd = t >> 5;

    __shared__ int wsum[4];
    __shared__ unsigned short sIdx[NN];

    const float* S = (MODE == 0 ? g_y : g_E) + (size_t)b * NN * CC;
    float ps = 0.f, ps2 = 0.f;

    for (int r = 0; r < AGG_R; r++) {
        int n = n0 + r;
        unsigned int w = g_Hb[((size_t)b * NN + n) * (NN / 32) + t];
        int cnt = __popc(w);
        int pre = cnt;
        #pragma unroll
        for (int o = 1; o < 32; o <<= 1) {
            int v = __shfl_up_sync(0xffffffffu, pre, o);
            if (lane >= o) pre += v;
        }
        if (lane == 31) wsum[wd] = pre;
        __syncthreads();
        int wbase = 0;
        #pragma unroll
        for (int k = 0; k < 4; k++) if (k < wd) wbase += wsum[k];
        int deg = wsum[0] + wsum[1] + wsum[2] + wsum[3];
        int kpos = wbase + pre - cnt;
        unsigned int ww = w;
        while (ww) {
            int q = __ffs(ww) - 1;
            ww &= ww - 1;
            sIdx[kpos++] = (unsigned short)(t * 32 + q);
        }
        __syncthreads();

        float acc = 0.f;
        for (int i = 0; i < deg; i++)
            acc += S[(size_t)sIdx[i] * CC + t];
        float inv = (deg > 0) ? (1.0f / (float)deg) : 0.0f;
        float v = acc * inv;
        size_t o = ((size_t)b * NN + n) * CC + t;
        if (MODE == 0) {
            g_E[o] = v;
        } else {
            float xe = g_y[o] + v;
            g_xe[o] = xe;
            ps += xe; ps2 += xe * xe;
        }
        __syncthreads();
    }
    if (MODE == 1) {
        int slot = b * (NN / AGG_R) + blockIdx.x;     // 0..511
        g_part2[slot][0][t] = ps;
        g_part2[slot][1][t] = ps2;
    }
}

// ---------------- K6: finalize stats -----------------------------------------
__global__ void stats_p2() {
    int c = threadIdx.x;
    float s = 0.f, s2 = 0.f;
    #pragma unroll 8
    for (int k = 0; k < 512; k++) { s += g_part2[k][0][c]; s2 += g_part2[k][1][c]; }
    float mean = s / (float)(BB * NN);
    float var = s2 / (float)(BB * NN) - mean * mean;
    g_mean[c] = mean;
    g_rstd[c] = rsqrtf(var + BN_EPS);
}

// ---------------- K7: BN + SiLU + transpose back to NCHW ---------------------
__global__ void out_kernel(const float* __restrict__ gamma,
                           const float* __restrict__ beta,
                           float* __restrict__ out) {
    __shared__ float tile[32][33];
    int b = blockIdx.z;
    int n0 = blockIdx.x * 32;
    int c0 = blockIdx.y * 32;
    int tx = threadIdx.x, ty = threadIdx.y;
    #pragma unroll
    for (int r = 0; r < 32; r += 8)
        tile[ty + r][tx] = g_xe[((size_t)b * NN + n0 + ty + r) * CC + c0 + tx];
    __syncthreads();
    #pragma unroll
    for (int r = 0; r < 32; r += 8) {
        int c = c0 + ty + r;
        float v = tile[tx][ty + r];
        float xn = gamma[c] * ((v - g_mean[c]) * g_rstd[c]) + beta[c];
        float sig = 1.0f / (1.0f + expf(-xn));
        out[((size_t)b * CC + c) * NN + n0 + tx] = xn * sig;
    }
}

// ---------------- entry ------------------------------------------------------
extern "C" void kernel_launch(void* const* d_in, const int* in_sizes, int n_in,
                              void* d_out, int out_size) {
    const float* x     = (const float*)d_in[0];
    const float* Wfc   = (const float*)d_in[1];
    const float* bfc   = (const float*)d_in[2];
    const float* gamma = (const float*)d_in[3];
    const float* beta  = (const float*)d_in[4];
    float* out = (float*)d_out;

    cudaFuncSetAttribute(gemm_y_mma, cudaFuncAttributeMaxDynamicSharedMemorySize, YS_TOTAL);
    cudaFuncSetAttribute(gemm_H_mma, cudaFuncAttributeMaxDynamicSharedMemorySize, HS_TOTAL);

    dim3 tb(32, 8);
    wprep_kernel<<<16, 1024>>>(Wfc);
    transpose_kernel<<<dim3(NN / 32, BB), tb>>>(x);
    gemm_y_mma<<<dim3(NN / 64, BB), 256, YS_TOTAL>>>(bfc);
    gemm_H_mma<<<dim3(528, BB), 256, HS_TOTAL>>>();
    agg_kernel<0><<<dim3(NN / AGG_R, BB), 128>>>();
    agg_kernel<1><<<dim3(NN / AGG_R, BB), 128>>>();
    stats_p2<<<1, 128>>>();
    out_kernel<<<dim3(NN / 32, CC / 32, BB), tb>>>(gamma, beta, out);
}

// round 6
// speedup vs baseline: 1.3186x; 1.3186x over previous
#include <cuda_runtime.h>
#include <cuda_bf16.h>
#include <cstdint>

#define BB 2
#define CC 128
#define NN 4096
#define THRESH2 64.0f
#define BN_EPS 1e-5f

// ---------------- scratch (device globals) -----------------------------------
__device__ __nv_bfloat16 g_xb[BB * NN * CC];
__device__ __nv_bfloat16 g_xl[BB * NN * CC];
__device__ __nv_bfloat16 g_Whi[CC * CC];
__device__ __nv_bfloat16 g_Wlo[CC * CC];
__device__ float g_sq[BB * NN];
__device__ float g_y [BB * NN * CC];
__device__ unsigned int g_Hb[(size_t)BB * NN * (NN / 32)];
__device__ float g_E [BB * NN * CC];
__device__ float g_xe[BB * NN * CC];
__device__ float g_partT[2][CC][1024];                // [s|s2][c][slot]
__device__ float g_mean[CC];
__device__ float g_rstd[CC];
__device__ unsigned int g_barcnt = 0;
__device__ unsigned int g_bargen = 0;

__device__ __forceinline__ uint32_t smem_u32(const void* p) {
    uint32_t a;
    asm("{ .reg .u64 t; cvta.to.shared.u64 t, %1; cvt.u32.u64 %0, t; }" : "=r"(a) : "l"(p));
    return a;
}
__device__ __forceinline__ void ldm_x4(uint32_t a[4], uint32_t addr) {
    asm volatile("ldmatrix.sync.aligned.m8n8.x4.shared.b16 {%0,%1,%2,%3}, [%4];"
                 : "=r"(a[0]), "=r"(a[1]), "=r"(a[2]), "=r"(a[3]) : "r"(addr));
}
__device__ __forceinline__ void mma16816(float c[4], const uint32_t a[4], const uint32_t b[2]) {
    asm volatile(
        "mma.sync.aligned.m16n8k16.row.col.f32.bf16.bf16.f32 "
        "{%0,%1,%2,%3}, {%4,%5,%6,%7}, {%8,%9}, {%0,%1,%2,%3};"
        : "+f"(c[0]), "+f"(c[1]), "+f"(c[2]), "+f"(c[3])
        : "r"(a[0]), "r"(a[1]), "r"(a[2]), "r"(a[3]), "r"(b[0]), "r"(b[1]));
}

// ---------------- K1: transpose + hi/lo split + sq  (+ W prep blocks) --------
__global__ void prep_kernel(const float* __restrict__ x, const float* __restrict__ Wfc) {
    int b = blockIdx.y;
    int tx = threadIdx.x, ty = threadIdx.y;
    int tid = ty * 32 + tx;

    if (blockIdx.x == NN / 32) {               // W split: 8192 elems per b
        #pragma unroll
        for (int k = 0; k < 32; k++) {
            int i = b * 8192 + tid + k * 256;
            float v = Wfc[i];
            __nv_bfloat16 h = __float2bfloat16(v);
            g_Whi[i] = h;
            g_Wlo[i] = __float2bfloat16(v - __bfloat162float(h));
        }
        return;
    }

    __shared__ float tile[32][33];
    int n0 = blockIdx.x * 32;
    float sq_acc[4] = {0.f, 0.f, 0.f, 0.f};

    for (int ct = 0; ct < 4; ct++) {
        int c0 = ct * 32;
        if (ct) __syncthreads();
        #pragma unroll
        for (int r = 0; r < 32; r += 8)
            tile[ty + r][tx] = x[((size_t)b * CC + c0 + ty + r) * NN + n0 + tx];
        __syncthreads();
        #pragma unroll
        for (int rr = 0; rr < 4; rr++) {
            int r = rr * 8;
            float v = tile[tx][ty + r];
            size_t o = ((size_t)b * NN + n0 + ty + r) * CC + c0 + tx;
            __nv_bfloat16 h = __float2bfloat16(v);
            g_xb[o] = h;
            g_xl[o] = __float2bfloat16(v - __bfloat162float(h));
            float s = v * v;
            #pragma unroll
            for (int o2 = 16; o2 > 0; o2 >>= 1) s += __shfl_xor_sync(0xffffffffu, s, o2);
            sq_acc[rr] += s;
        }
    }
    if (tx == 0) {
        #pragma unroll
        for (int rr = 0; rr < 4; rr++)
            g_sq[(size_t)b * NN + n0 + ty + rr * 8] = sq_acc[rr];
    }
}

// ---------------- K2: fused gemm (H tiles + y tiles) -------------------------
#define HS_SQI 0
#define HS_SQJ 512
#define HS_A   1024
#define HS_B   33792
#define HS_H   66560
#define SH_STRIDE 144
#define YS_AH 0
#define YS_AL 16384
#define YS_WH 32768
#define YS_WL 65536
#define GM_SMEM 98304

__device__ void gemm_H_path(char* smem, int b, int tile_idx) {
    int tid = threadIdx.x;
    int wid = tid >> 5, lane = tid & 31;

    int idx = tile_idx, ti = 0, rem = 32;
    while (idx >= rem) { idx -= rem; ti++; rem--; }
    int tj = ti + idx;
    int n0 = ti * 128, m0 = tj * 128;

    float* sSqI = (float*)(smem + HS_SQI);
    float* sSqJ = (float*)(smem + HS_SQJ);
    if (tid < 128) {
        sSqI[tid] = g_sq[(size_t)b * NN + n0 + tid];
        sSqJ[tid] = g_sq[(size_t)b * NN + m0 + tid];
    }
    {
        const uint4* Ag = (const uint4*)(g_xb + ((size_t)b * NN + n0) * CC);
        const uint4* Bg = (const uint4*)(g_xb + ((size_t)b * NN + m0) * CC);
        #pragma unroll
        for (int it = 0; it < 8; it++) {
            int id = tid + it * 256;
            int row = id >> 4, ch = id & 15;
            int off = row * 256 + (ch ^ (row & 7)) * 16;
            *(uint4*)(smem + HS_A + off) = Ag[(size_t)row * 16 + ch];
            *(uint4*)(smem + HS_B + off) = Bg[(size_t)row * 16 + ch];
        }
    }
    __syncthreads();

    int warp_m = wid & 3, warp_n = wid >> 2;
    int mbase = warp_m * 32, nbase = warp_n * 64;

    float acc[2][8][4];
    #pragma unroll
    for (int mt = 0; mt < 2; mt++)
        #pragma unroll
        for (int nt = 0; nt < 8; nt++)
            #pragma unroll
            for (int q = 0; q < 4; q++) acc[mt][nt][q] = 0.f;

    uint32_t Abase = smem_u32(smem + HS_A);
    uint32_t Bbase = smem_u32(smem + HS_B);
    int a_row_local = lane & 15;
    int a_hi = lane >> 4;
    int bg = lane >> 3;
    int b_row_local = lane & 7;
    int b_nt_off = bg >> 1;
    int b_hi = bg & 1;

    #pragma unroll
    for (int kk = 0; kk < 8; kk++) {
        uint32_t afr[2][4];
        #pragma unroll
        for (int mt = 0; mt < 2; mt++) {
            int row = mbase + mt * 16 + a_row_local;
            int ch = (2 * kk + a_hi) ^ (row & 7);
            ldm_x4(afr[mt], Abase + row * 256 + ch * 16);
        }
        uint32_t bfr[8][2];
        #pragma unroll
        for (int nt2 = 0; nt2 < 4; nt2++) {
            int row = nbase + nt2 * 16 + b_nt_off * 8 + b_row_local;
            int ch = (2 * kk + b_hi) ^ (row & 7);
            uint32_t r4[4];
            ldm_x4(r4, Bbase + row * 256 + ch * 16);
            bfr[nt2 * 2][0] = r4[0]; bfr[nt2 * 2][1] = r4[1];
            bfr[nt2 * 2 + 1][0] = r4[2]; bfr[nt2 * 2 + 1][1] = r4[3];
        }
        #pragma unroll
        for (int mt = 0; mt < 2; mt++)
            #pragma unroll
            for (int nt = 0; nt < 8; nt++)
                mma16816(acc[mt][nt], afr[mt], bfr[nt]);
    }

    unsigned char* sH = (unsigned char*)(smem + HS_H);
    int rrow = lane >> 2;
    int ccol = (lane & 3) * 2;
    #pragma unroll
    for (int mt = 0; mt < 2; mt++) {
        #pragma unroll
        for (int nt = 0; nt < 8; nt++) {
            int col = nbase + nt * 8 + ccol;
            float sm0 = sSqJ[col], sm1 = sSqJ[col + 1];
            #pragma unroll
            for (int h = 0; h < 2; h++) {
                int row = mbase + mt * 16 + rrow + h * 8;
                float sqn = sSqI[row];
                float d20 = sqn + sm0 - 2.0f * acc[mt][nt][h * 2 + 0];
                float d21 = sqn + sm1 - 2.0f * acc[mt][nt][h * 2 + 1];
                sH[row * SH_STRIDE + col]     = (d20 < THRESH2) ? 1 : 0;
                sH[row * SH_STRIDE + col + 1] = (d21 < THRESH2) ? 1 : 0;
            }
        }
    }
    __syncthreads();

    unsigned int* Hb = g_Hb + (size_t)b * NN * (NN / 32);
    #pragma unroll
    for (int it = 0; it < 2; it++) {
        int id = tid + it * 256;
        int row = id >> 2, w = id & 3;
        const unsigned int* src = (const unsigned int*)(sH + row * SH_STRIDE + w * 32);
        unsigned int bits = 0;
        #pragma unroll
        for (int k = 0; k < 8; k++) {
            unsigned int u = src[k];
            bits |= (u & 1u) << (k * 4);
            bits |= ((u >> 8) & 1u) << (k * 4 + 1);
            bits |= ((u >> 16) & 1u) << (k * 4 + 2);
            bits |= ((u >> 24) & 1u) << (k * 4 + 3);
        }
        Hb[(size_t)(n0 + row) * (NN / 32) + (m0 >> 5) + w] = bits;
    }
    if (ti != tj && tid < 128) {
        int mrow = tid;
        unsigned int wbits[4];
        #pragma unroll
        for (int w = 0; w < 4; w++) {
            unsigned int bits = 0;
            #pragma unroll
            for (int q = 0; q < 32; q++)
                bits |= (unsigned int)(sH[(w * 32 + q) * SH_STRIDE + mrow] & 1u) << q;
            wbits[w] = bits;
        }
        *(uint4*)&Hb[(size_t)(m0 + mrow) * (NN / 32) + (n0 >> 5)] =
            make_uint4(wbits[0], wbits[1], wbits[2], wbits[3]);
    }
}

__device__ void gemm_y_path(char* smem, int b, int ytile, const float* __restrict__ bfc) {
    int tid = threadIdx.x;
    int wid = tid >> 5, lane = tid & 31;
    int n0 = ytile * 64;

    {
        const uint4* Ah = (const uint4*)(g_xb + ((size_t)b * NN + n0) * CC);
        const uint4* Al = (const uint4*)(g_xl + ((size_t)b * NN + n0) * CC);
        #pragma unroll
        for (int it = 0; it < 4; it++) {
            int id = tid + it * 256;
            int row = id >> 4, ch = id & 15;
            int off = row * 256 + (ch ^ (row & 7)) * 16;
            *(uint4*)(smem + YS_AH + off) = Ah[(size_t)row * 16 + ch];
            *(uint4*)(smem + YS_AL + off) = Al[(size_t)row * 16 + ch];
        }
        const uint4* Wh = (const uint4*)g_Whi;
        const uint4* Wl = (const uint4*)g_Wlo;
        #pragma unroll
        for (int it = 0; it < 8; it++) {
            int id = tid + it * 256;
            int row = id >> 4, ch = id & 15;
            int off = row * 256 + (ch ^ (row & 7)) * 16;
            *(uint4*)(smem + YS_WH + off) = Wh[(size_t)row * 16 + ch];
            *(uint4*)(smem + YS_WL + off) = Wl[(size_t)row * 16 + ch];
        }
    }
    __syncthreads();

    int warp_m = wid & 1, warp_n = wid >> 1;
    int mbase = warp_m * 32, nbase = warp_n * 32;

    float acc[2][4][4];
    #pragma unroll
    for (int mt = 0; mt < 2; mt++)
        #pragma unroll
        for (int nt = 0; nt < 4; nt++)
            #pragma unroll
            for (int q = 0; q < 4; q++) acc[mt][nt][q] = 0.f;

    int a_row_local = lane & 15;
    int a_hi = lane >> 4;
    int bg = lane >> 3;
    int b_row_local = lane & 7;
    int b_nt_off = bg >> 1;
    int b_hi = bg & 1;

    #pragma unroll
    for (int pass = 0; pass < 3; pass++) {
        uint32_t Abase = smem_u32(smem + (pass == 2 ? YS_AL : YS_AH));
        uint32_t Bbase = smem_u32(smem + (pass == 1 ? YS_WL : YS_WH));
        #pragma unroll
        for (int kk = 0; kk < 8; kk++) {
            uint32_t afr[2][4];
            #pragma unroll
            for (int mt = 0; mt < 2; mt++) {
                int row = mbase + mt * 16 + a_row_local;
                int ch = (2 * kk + a_hi) ^ (row & 7);
                ldm_x4(afr[mt], Abase + row * 256 + ch * 16);
            }
            uint32_t bfr[4][2];
            #pragma unroll
            for (int nt2 = 0; nt2 < 2; nt2++) {
                int row = nbase + nt2 * 16 + b_nt_off * 8 + b_row_local;
                int ch = (2 * kk + b_hi) ^ (row & 7);
                uint32_t r4[4];
                ldm_x4(r4, Bbase + row * 256 + ch * 16);
                bfr[nt2 * 2][0] = r4[0]; bfr[nt2 * 2][1] = r4[1];
                bfr[nt2 * 2 + 1][0] = r4[2]; bfr[nt2 * 2 + 1][1] = r4[3];
            }
            #pragma unroll
            for (int mt = 0; mt < 2; mt++)
                #pragma unroll
                for (int nt = 0; nt < 4; nt++)
                    mma16816(acc[mt][nt], afr[mt], bfr[nt]);
        }
    }

    int rrow = lane >> 2;
    int ccol = (lane & 3) * 2;
    float* Y = g_y + ((size_t)b * NN + n0) * CC;
    #pragma unroll
    for (int mt = 0; mt < 2; mt++) {
        #pragma unroll
        for (int nt = 0; nt < 4; nt++) {
            int col = nbase + nt * 8 + ccol;
            float b0 = bfc[col], b1 = bfc[col + 1];
            #pragma unroll
            for (int h = 0; h < 2; h++) {
                int row = mbase + mt * 16 + rrow + h * 8;
                Y[(size_t)row * CC + col]     = acc[mt][nt][h * 2 + 0] + b0;
                Y[(size_t)row * CC + col + 1] = acc[mt][nt][h * 2 + 1] + b1;
            }
        }
    }
}

__global__ void __launch_bounds__(256, 2) gemm_fused(const float* __restrict__ bfc) {
    extern __shared__ char smem[];
    int b = blockIdx.y;
    if (blockIdx.x < 528) gemm_H_path(smem, b, blockIdx.x);
    else                  gemm_y_path(smem, b, blockIdx.x - 528, bfc);
}

// ---------------- K3: mega tail (agg0 -> agg1+stats -> finalize -> out) ------
#define TAIL_BLOCKS 512

__device__ __forceinline__ void grid_bar() {
    __syncthreads();
    if (threadIdx.x == 0) {
        __threadfence();
        unsigned int gen = *((volatile unsigned int*)&g_bargen);
        if (atomicAdd(&g_barcnt, 1u) == TAIL_BLOCKS - 1) {
            g_barcnt = 0;
            __threadfence();
            *((volatile unsigned int*)&g_bargen) = gen + 1;
        } else {
            while (*((volatile unsigned int*)&g_bargen) == gen) __nanosleep(64);
        }
    }
    __syncthreads();
}

template <int MODE>
__device__ void agg_phase(int b, int n0, unsigned short (*sIdx)[NN], int* wsum,
                          float& ps, float& ps2) {
    int tid = threadIdx.x;
    int h = tid >> 7;                          // half: row parity
    int c = tid & 127;                         // channel AND word index
    int lane = tid & 31;
    int wd = (tid >> 5) & 3;
    const float* S = (MODE == 0 ? g_y : g_E) + (size_t)b * NN * CC;
    const float* Yb = g_y + (size_t)b * NN * CC;

    for (int i = 0; i < 8; i++) {
        int n = n0 + i * 2 + h;
        unsigned int w = g_Hb[((size_t)b * NN + n) * (NN / 32) + c];
        int cnt = __popc(w);
        int pre = cnt;
        #pragma unroll
        for (int o = 1; o < 32; o <<= 1) {
            int v = __shfl_up_sync(0xffffffffu, pre, o);
            if (lane >= o) pre += v;
        }
        if (lane == 31) wsum[h * 4 + wd] = pre;
        __syncthreads();
        int wbase = 0;
        #pragma unroll
        for (int k = 0; k < 4; k++) if (k < wd) wbase += wsum[h * 4 + k];
        int deg = wsum[h * 4] + wsum[h * 4 + 1] + wsum[h * 4 + 2] + wsum[h * 4 + 3];
        int kpos = wbase + pre - cnt;
        unsigned int ww = w;
        while (ww) {
            int q = __ffs(ww) - 1;
            ww &= ww - 1;
            sIdx[h][kpos++] = (unsigned short)(c * 32 + q);
        }
        __syncthreads();

        float acc = 0.f;
        for (int ii = 0; ii < deg; ii++) {
            int m = sIdx[h][ii];
            acc += (MODE == 0) ? S[(size_t)m * CC + c]
                               : __ldcg(&S[(size_t)m * CC + c]);
        }
        float inv = (deg > 0) ? (1.0f / (float)deg) : 0.0f;
        float v = acc * inv;
        size_t o = ((size_t)b * NN + n) * CC + c;
        if (MODE == 0) {
            g_E[o] = v;
        } else {
            float xe = Yb[(size_t)n * CC + c] + v;
            g_xe[o] = xe;
            ps += xe; ps2 += xe * xe;
        }
        __syncthreads();
    }
}

__global__ void __launch_bounds__(256, 4) tail_kernel(const float* __restrict__ gamma,
                                                      const float* __restrict__ beta,
                                                      float* __restrict__ out) {
    __shared__ unsigned short sIdx[2][NN];     // 16 KB
    __shared__ int wsum[8];
    __shared__ float tile[32][65];             // 8.3 KB (out phase)
    __shared__ float red[2][32];

    int bx = blockIdx.x;
    int tid = threadIdx.x;
    int b = bx >> 8;
    int n0 = (bx & 255) * 16;
    int h = tid >> 7, c = tid & 127;

    float ps = 0.f, ps2 = 0.f;

    // phase A: E = (H@y)/deg
    agg_phase<0>(b, n0, sIdx, wsum, ps, ps2);
    grid_bar();
    // phase B: xe = y + (H@E)/deg, accumulate BN partials
    agg_phase<1>(b, n0, sIdx, wsum, ps, ps2);
    {
        int slot = bx * 2 + h;                 // 0..1023
        g_partT[0][c][slot] = ps;
        g_partT[1][c][slot] = ps2;
    }
    grid_bar();
    // phase C: finalize stats, blocks 0..127 (block = channel)
    if (bx < CC) {
        int ch = bx;
        float s = 0.f, s2 = 0.f;
        #pragma unroll
        for (int k = 0; k < 4; k++) {
            int slot = tid + k * 256;
            s  += __ldcg(&g_partT[0][ch][slot]);
            s2 += __ldcg(&g_partT[1][ch][slot]);
        }
        int lane = tid & 31, wd = tid >> 5;
        #pragma unroll
        for (int o = 16; o > 0; o >>= 1) {
            s  += __shfl_xor_sync(0xffffffffu, s,  o);
            s2 += __shfl_xor_sync(0xffffffffu, s2, o);
        }
        if (lane == 0) { red[0][wd] = s; red[1][wd] = s2; }
        __syncthreads();
        if (tid == 0) {
            float ts = 0.f, ts2 = 0.f;
            #pragma unroll
            for (int k = 0; k < 8; k++) { ts += red[0][k]; ts2 += red[1][k]; }
            float mean = ts / (float)(BB * NN);
            float var = ts2 / (float)(BB * NN) - mean * mean;
            g_mean[ch] = mean;
            g_rstd[ch] = rsqrtf(var + BN_EPS);
        }
    }
    grid_bar();
    // phase D: BN + SiLU + transpose to NCHW.  region: 32 n x 64 c
    {
        int rem = bx & 255;
        int b2 = bx >> 8;
        int n0o = (rem >> 1) * 32;
        int c0o = (rem & 1) * 64;
        #pragma unroll
        for (int i = 0; i < 8; i++) {
            int idx = tid + i * 256;
            int nl = idx >> 6, cl = idx & 63;
            tile[nl][cl] = __ldcg(&g_xe[((size_t)b2 * NN + n0o + nl) * CC + c0o + cl]);
        }
        __syncthreads();
        #pragma unroll
        for (int i = 0; i < 8; i++) {
            int idx = tid + i * 256;
            int cl = idx >> 5, nl = idx & 31;
            int ch = c0o + cl;
            float v = tile[nl][cl];
            float xn = gamma[ch] * ((v - __ldcg(&g_mean[ch])) * __ldcg(&g_rstd[ch])) + beta[ch];
            float sig = 1.0f / (1.0f + expf(-xn));
            out[((size_t)b2 * CC + ch) * NN + n0o + nl] = xn * sig;
        }
    }
}

// ---------------- entry ------------------------------------------------------
extern "C" void kernel_launch(void* const* d_in, const int* in_sizes, int n_in,
                              void* d_out, int out_size) {
    const float* x     = (const float*)d_in[0];
    const float* Wfc   = (const float*)d_in[1];
    const float* bfc   = (const float*)d_in[2];
    const float* gamma = (const float*)d_in[3];
    const float* beta  = (const float*)d_in[4];
    float* out = (float*)d_out;

    cudaFuncSetAttribute(gemm_fused, cudaFuncAttributeMaxDynamicSharedMemorySize, GM_SMEM);

    prep_kernel<<<dim3(NN / 32 + 1, BB), dim3(32, 8)>>>(x, Wfc);
    gemm_fused<<<dim3(592, BB), 256, GM_SMEM>>>(bfc);
    tail_kernel<<<TAIL_BLOCKS, 256>>>(gamma, beta, out);
}

// round 7
// speedup vs baseline: 1.5619x; 1.1845x over previous
#include <cuda_runtime.h>
#include <cuda_bf16.h>
#include <cstdint>

#define BB 2
#define CC 128
#define NN 4096
#define THRESH2 64.0f
#define BN_EPS 1e-5f

// ---------------- scratch (device globals) -----------------------------------
__device__ __nv_bfloat16 g_xb[BB * NN * CC];
__device__ __nv_bfloat16 g_xl[BB * NN * CC];
__device__ __nv_bfloat16 g_Whi[CC * CC];
__device__ __nv_bfloat16 g_Wlo[CC * CC];
__device__ float g_sq[BB * NN];
__device__ float g_y [BB * NN * CC];
__device__ unsigned int g_Hb[(size_t)BB * NN * (NN / 32)];
__device__ float g_E [BB * NN * CC];
__device__ float g_xe[BB * NN * CC];
__device__ float g_partT[2][CC][512];                 // [s|s2][c][block]
__device__ float g_mean[CC];
__device__ float g_rstd[CC];
__device__ unsigned int g_barcnt = 0;
__device__ unsigned int g_bargen = 0;

__device__ __forceinline__ uint32_t smem_u32(const void* p) {
    uint32_t a;
    asm("{ .reg .u64 t; cvta.to.shared.u64 t, %1; cvt.u32.u64 %0, t; }" : "=r"(a) : "l"(p));
    return a;
}
__device__ __forceinline__ void ldm_x4(uint32_t a[4], uint32_t addr) {
    asm volatile("ldmatrix.sync.aligned.m8n8.x4.shared.b16 {%0,%1,%2,%3}, [%4];"
                 : "=r"(a[0]), "=r"(a[1]), "=r"(a[2]), "=r"(a[3]) : "r"(addr));
}
__device__ __forceinline__ void mma16816(float c[4], const uint32_t a[4], const uint32_t b[2]) {
    asm volatile(
        "mma.sync.aligned.m16n8k16.row.col.f32.bf16.bf16.f32 "
        "{%0,%1,%2,%3}, {%4,%5,%6,%7}, {%8,%9}, {%0,%1,%2,%3};"
        : "+f"(c[0]), "+f"(c[1]), "+f"(c[2]), "+f"(c[3])
        : "r"(a[0]), "r"(a[1]), "r"(a[2]), "r"(a[3]), "r"(b[0]), "r"(b[1]));
}

// ---------------- K1: transpose + hi/lo split + sq  (+ W prep blocks) --------
// grid (NN/32 + 1, CC/32, BB), block (32,8)
__global__ void prep_kernel(const float* __restrict__ x, const float* __restrict__ Wfc) {
    int b = blockIdx.z;
    int tx = threadIdx.x, ty = threadIdx.y;
    int tid = ty * 32 + tx;

    if (blockIdx.x == NN / 32) {               // W split: 8 blocks x 2048 elems
        int base = (b * 4 + blockIdx.y) * 2048;
        #pragma unroll
        for (int k = 0; k < 8; k++) {
            int i = base + tid + k * 256;
            float v = Wfc[i];
            __nv_bfloat16 h = __float2bfloat16(v);
            g_Whi[i] = h;
            g_Wlo[i] = __float2bfloat16(v - __bfloat162float(h));
        }
        return;
    }

    __shared__ float tile[32][33];
    int c0 = blockIdx.y * 32;
    int n0 = blockIdx.x * 32;
    #pragma unroll
    for (int r = 0; r < 32; r += 8)
        tile[ty + r][tx] = x[((size_t)b * CC + c0 + ty + r) * NN + n0 + tx];
    __syncthreads();
    #pragma unroll
    for (int r = 0; r < 32; r += 8) {
        float v = tile[tx][ty + r];
        size_t o = ((size_t)b * NN + n0 + ty + r) * CC + c0 + tx;
        __nv_bfloat16 h = __float2bfloat16(v);
        g_xb[o] = h;
        g_xl[o] = __float2bfloat16(v - __bfloat162float(h));
        float s = v * v;
        #pragma unroll
        for (int o2 = 16; o2 > 0; o2 >>= 1) s += __shfl_xor_sync(0xffffffffu, s, o2);
        if (tx == 0) atomicAdd(&g_sq[(size_t)b * NN + n0 + ty + r], s);
    }
}

// ---------------- K2: fused gemm (H tiles + y tiles) -------------------------
#define HS_SQI 0
#define HS_SQJ 512
#define HS_A   1024
#define HS_B   33792
#define HS_H   66560
#define SH_STRIDE 144
#define YS_AH 0
#define YS_AL 16384
#define YS_WH 32768
#define YS_WL 65536
#define GM_SMEM 98304

__device__ void gemm_H_path(char* smem, int b, int tile_idx) {
    int tid = threadIdx.x;
    int wid = tid >> 5, lane = tid & 31;

    int idx = tile_idx, ti = 0, rem = 32;
    while (idx >= rem) { idx -= rem; ti++; rem--; }
    int tj = ti + idx;
    int n0 = ti * 128, m0 = tj * 128;

    float* sSqI = (float*)(smem + HS_SQI);
    float* sSqJ = (float*)(smem + HS_SQJ);
    if (tid < 128) {
        sSqI[tid] = g_sq[(size_t)b * NN + n0 + tid];
        sSqJ[tid] = g_sq[(size_t)b * NN + m0 + tid];
    }
    {
        const uint4* Ag = (const uint4*)(g_xb + ((size_t)b * NN + n0) * CC);
        const uint4* Bg = (const uint4*)(g_xb + ((size_t)b * NN + m0) * CC);
        #pragma unroll
        for (int it = 0; it < 8; it++) {
            int id = tid + it * 256;
            int row = id >> 4, ch = id & 15;
            int off = row * 256 + (ch ^ (row & 7)) * 16;
            *(uint4*)(smem + HS_A + off) = Ag[(size_t)row * 16 + ch];
            *(uint4*)(smem + HS_B + off) = Bg[(size_t)row * 16 + ch];
        }
    }
    __syncthreads();

    int warp_m = wid & 3, warp_n = wid >> 2;
    int mbase = warp_m * 32, nbase = warp_n * 64;

    float acc[2][8][4];
    #pragma unroll
    for (int mt = 0; mt < 2; mt++)
        #pragma unroll
        for (int nt = 0; nt < 8; nt++)
            #pragma unroll
            for (int q = 0; q < 4; q++) acc[mt][nt][q] = 0.f;

    uint32_t Abase = smem_u32(smem + HS_A);
    uint32_t Bbase = smem_u32(smem + HS_B);
    int a_row_local = lane & 15;
    int a_hi = lane >> 4;
    int bg = lane >> 3;
    int b_row_local = lane & 7;
    int b_nt_off = bg >> 1;
    int b_hi = bg & 1;

    #pragma unroll
    for (int kk = 0; kk < 8; kk++) {
        uint32_t afr[2][4];
        #pragma unroll
        for (int mt = 0; mt < 2; mt++) {
            int row = mbase + mt * 16 + a_row_local;
            int ch = (2 * kk + a_hi) ^ (row & 7);
            ldm_x4(afr[mt], Abase + row * 256 + ch * 16);
        }
        uint32_t bfr[8][2];
        #pragma unroll
        for (int nt2 = 0; nt2 < 4; nt2++) {
            int row = nbase + nt2 * 16 + b_nt_off * 8 + b_row_local;
            int ch = (2 * kk + b_hi) ^ (row & 7);
            uint32_t r4[4];
            ldm_x4(r4, Bbase + row * 256 + ch * 16);
            bfr[nt2 * 2][0] = r4[0]; bfr[nt2 * 2][1] = r4[1];
            bfr[nt2 * 2 + 1][0] = r4[2]; bfr[nt2 * 2 + 1][1] = r4[3];
        }
        #pragma unroll
        for (int mt = 0; mt < 2; mt++)
            #pragma unroll
            for (int nt = 0; nt < 8; nt++)
                mma16816(acc[mt][nt], afr[mt], bfr[nt]);
    }

    unsigned char* sH = (unsigned char*)(smem + HS_H);
    int rrow = lane >> 2;
    int ccol = (lane & 3) * 2;
    #pragma unroll
    for (int mt = 0; mt < 2; mt++) {
        #pragma unroll
        for (int nt = 0; nt < 8; nt++) {
            int col = nbase + nt * 8 + ccol;
            float sm0 = sSqJ[col], sm1 = sSqJ[col + 1];
            #pragma unroll
            for (int h = 0; h < 2; h++) {
                int row = mbase + mt * 16 + rrow + h * 8;
                float sqn = sSqI[row];
                float d20 = sqn + sm0 - 2.0f * acc[mt][nt][h * 2 + 0];
                float d21 = sqn + sm1 - 2.0f * acc[mt][nt][h * 2 + 1];
                sH[row * SH_STRIDE + col]     = (d20 < THRESH2) ? 1 : 0;
                sH[row * SH_STRIDE + col + 1] = (d21 < THRESH2) ? 1 : 0;
            }
        }
    }
    __syncthreads();

    unsigned int* Hb = g_Hb + (size_t)b * NN * (NN / 32);
    #pragma unroll
    for (int it = 0; it < 2; it++) {
        int id = tid + it * 256;
        int row = id >> 2, w = id & 3;
        const unsigned int* src = (const unsigned int*)(sH + row * SH_STRIDE + w * 32);
        unsigned int bits = 0;
        #pragma unroll
        for (int k = 0; k < 8; k++) {
            unsigned int u = src[k];
            bits |= (u & 1u) << (k * 4);
            bits |= ((u >> 8) & 1u) << (k * 4 + 1);
            bits |= ((u >> 16) & 1u) << (k * 4 + 2);
            bits |= ((u >> 24) & 1u) << (k * 4 + 3);
        }
        Hb[(size_t)(n0 + row) * (NN / 32) + (m0 >> 5) + w] = bits;
    }
    if (ti != tj && tid < 128) {
        int mrow = tid;
        unsigned int wbits[4];
        #pragma unroll
        for (int w = 0; w < 4; w++) {
            unsigned int bits = 0;
            #pragma unroll
            for (int q = 0; q < 32; q++)
                bits |= (unsigned int)(sH[(w * 32 + q) * SH_STRIDE + mrow] & 1u) << q;
            wbits[w] = bits;
        }
        *(uint4*)&Hb[(size_t)(m0 + mrow) * (NN / 32) + (n0 >> 5)] =
            make_uint4(wbits[0], wbits[1], wbits[2], wbits[3]);
    }
}

__device__ void gemm_y_path(char* smem, int b, int ytile, const float* __restrict__ bfc) {
    int tid = threadIdx.x;
    int wid = tid >> 5, lane = tid & 31;
    int n0 = ytile * 64;

    {
        const uint4* Ah = (const uint4*)(g_xb + ((size_t)b * NN + n0) * CC);
        const uint4* Al = (const uint4*)(g_xl + ((size_t)b * NN + n0) * CC);
        #pragma unroll
        for (int it = 0; it < 4; it++) {
            int id = tid + it * 256;
            int row = id >> 4, ch = id & 15;
            int off = row * 256 + (ch ^ (row & 7)) * 16;
            *(uint4*)(smem + YS_AH + off) = Ah[(size_t)row * 16 + ch];
            *(uint4*)(smem + YS_AL + off) = Al[(size_t)row * 16 + ch];
        }
        const uint4* Wh = (const uint4*)g_Whi;
        const uint4* Wl = (const uint4*)g_Wlo;
        #pragma unroll
        for (int it = 0; it < 8; it++) {
            int id = tid + it * 256;
            int row = id >> 4, ch = id & 15;
            int off = row * 256 + (ch ^ (row & 7)) * 16;
            *(uint4*)(smem + YS_WH + off) = Wh[(size_t)row * 16 + ch];
            *(uint4*)(smem + YS_WL + off) = Wl[(size_t)row * 16 + ch];
        }
    }
    __syncthreads();

    int warp_m = wid & 1, warp_n = wid >> 1;
    int mbase = warp_m * 32, nbase = warp_n * 32;

    float acc[2][4][4];
    #pragma unroll
    for (int mt = 0; mt < 2; mt++)
        #pragma unroll
        for (int nt = 0; nt < 4; nt++)
            #pragma unroll
            for (int q = 0; q < 4; q++) acc[mt][nt][q] = 0.f;

    int a_row_local = lane & 15;
    int a_hi = lane >> 4;
    int bg = lane >> 3;
    int b_row_local = lane & 7;
    int b_nt_off = bg >> 1;
    int b_hi = bg & 1;

    #pragma unroll
    for (int pass = 0; pass < 3; pass++) {
        uint32_t Abase = smem_u32(smem + (pass == 2 ? YS_AL : YS_AH));
        uint32_t Bbase = smem_u32(smem + (pass == 1 ? YS_WL : YS_WH));
        #pragma unroll
        for (int kk = 0; kk < 8; kk++) {
            uint32_t afr[2][4];
            #pragma unroll
            for (int mt = 0; mt < 2; mt++) {
                int row = mbase + mt * 16 + a_row_local;
                int ch = (2 * kk + a_hi) ^ (row & 7);
                ldm_x4(afr[mt], Abase + row * 256 + ch * 16);
            }
            uint32_t bfr[4][2];
            #pragma unroll
            for (int nt2 = 0; nt2 < 2; nt2++) {
                int row = nbase + nt2 * 16 + b_nt_off * 8 + b_row_local;
                int ch = (2 * kk + b_hi) ^ (row & 7);
                uint32_t r4[4];
                ldm_x4(r4, Bbase + row * 256 + ch * 16);
                bfr[nt2 * 2][0] = r4[0]; bfr[nt2 * 2][1] = r4[1];
                bfr[nt2 * 2 + 1][0] = r4[2]; bfr[nt2 * 2 + 1][1] = r4[3];
            }
            #pragma unroll
            for (int mt = 0; mt < 2; mt++)
                #pragma unroll
                for (int nt = 0; nt < 4; nt++)
                    mma16816(acc[mt][nt], afr[mt], bfr[nt]);
        }
    }

    int rrow = lane >> 2;
    int ccol = (lane & 3) * 2;
    float* Y = g_y + ((size_t)b * NN + n0) * CC;
    #pragma unroll
    for (int mt = 0; mt < 2; mt++) {
        #pragma unroll
        for (int nt = 0; nt < 4; nt++) {
            int col = nbase + nt * 8 + ccol;
            float b0 = bfc[col], b1 = bfc[col + 1];
            #pragma unroll
            for (int h = 0; h < 2; h++) {
                int row = mbase + mt * 16 + rrow + h * 8;
                Y[(size_t)row * CC + col]     = acc[mt][nt][h * 2 + 0] + b0;
                Y[(size_t)row * CC + col + 1] = acc[mt][nt][h * 2 + 1] + b1;
            }
        }
    }
}

__global__ void __launch_bounds__(256, 2) gemm_fused(const float* __restrict__ bfc) {
    extern __shared__ char smem[];
    int b = blockIdx.y;
    if (blockIdx.x < 528) gemm_H_path(smem, b, blockIdx.x);
    else                  gemm_y_path(smem, b, blockIdx.x - 528, bfc);
}

// ---------------- K3: mega tail (warp-per-row agg, fused BN + out) -----------
#define TAIL_BLOCKS 512

__device__ __forceinline__ void grid_bar() {
    __syncthreads();
    if (threadIdx.x == 0) {
        __threadfence();
        unsigned int gen = *((volatile unsigned int*)&g_bargen);
        if (atomicAdd(&g_barcnt, 1u) == TAIL_BLOCKS - 1) {
            g_barcnt = 0;
            __threadfence();
            *((volatile unsigned int*)&g_bargen) = gen + 1;
        } else {
            while (*((volatile unsigned int*)&g_bargen) == gen) __nanosleep(64);
        }
    }
    __syncthreads();
}

// warp-per-row aggregation: 8 warps/block, 2 iterations -> 16 rows per block.
template <int MODE>
__device__ void agg_phase(int b, int n0, unsigned short (*sIdx)[512],
                          float4& ps, float4& ps2) {
    int tid = threadIdx.x;
    int w = tid >> 5, lane = tid & 31;
    const float* S = (MODE == 0 ? g_y : g_E) + (size_t)b * NN * CC;
    const float* Yb = g_y + (size_t)b * NN * CC;

    #pragma unroll
    for (int i = 0; i < 2; i++) {
        int n = n0 + i * 8 + w;
        const unsigned int* Hrow = g_Hb + ((size_t)b * NN + n) * (NN / 32);
        uint4 wv = ((const uint4*)Hrow)[lane];
        int cnt = __popc(wv.x) + __popc(wv.y) + __popc(wv.z) + __popc(wv.w);
        int pre = cnt;
        #pragma unroll
        for (int o = 1; o < 32; o <<= 1) {
            int t2 = __shfl_up_sync(0xffffffffu, pre, o);
            if (lane >= o) pre += t2;
        }
        int deg = __shfl_sync(0xffffffffu, pre, 31);
        float4 acc = make_float4(0.f, 0.f, 0.f, 0.f);
        const float* Scol = S + lane * 4;

        if (deg <= 512) {
            int kpos = pre - cnt;
            unsigned int arr[4] = {wv.x, wv.y, wv.z, wv.w};
            #pragma unroll
            for (int j = 0; j < 4; j++) {
                unsigned int bits = arr[j];
                while (bits) {
                    int q = __ffs(bits) - 1;
                    bits &= bits - 1;
                    sIdx[w][kpos++] = (unsigned short)(lane * 128 + j * 32 + q);
                }
            }
            __syncwarp();
            for (int ii = 0; ii < deg; ii++) {
                int m = sIdx[w][ii];
                float4 v = (MODE == 0)
                    ? *(const float4*)(Scol + (size_t)m * CC)
                    : __ldcg((const float4*)(Scol + (size_t)m * CC));
                acc.x += v.x; acc.y += v.y; acc.z += v.z; acc.w += v.w;
            }
        } else {
            for (int w2 = 0; w2 < NN / 32; w2++) {
                unsigned int bits = Hrow[w2];
                while (bits) {
                    int q = __ffs(bits) - 1;
                    bits &= bits - 1;
                    int m = w2 * 32 + q;
                    float4 v = (MODE == 0)
                        ? *(const float4*)(Scol + (size_t)m * CC)
                        : __ldcg((const float4*)(Scol + (size_t)m * CC));
                    acc.x += v.x; acc.y += v.y; acc.z += v.z; acc.w += v.w;
                }
            }
        }

        float inv = (deg > 0) ? (1.0f / (float)deg) : 0.0f;
        float4 vo = make_float4(acc.x * inv, acc.y * inv, acc.z * inv, acc.w * inv);
        size_t o = ((size_t)b * NN + n) * CC + lane * 4;
        if (MODE == 0) {
            *(float4*)&g_E[o] = vo;
        } else {
            float4 yv = *(const float4*)(Yb + (size_t)n * CC + lane * 4);
            float4 xe = make_float4(yv.x + vo.x, yv.y + vo.y, yv.z + vo.z, yv.w + vo.w);
            *(float4*)&g_xe[o] = xe;
            ps.x += xe.x; ps.y += xe.y; ps.z += xe.z; ps.w += xe.w;
            ps2.x += xe.x * xe.x; ps2.y += xe.y * xe.y;
            ps2.z += xe.z * xe.z; ps2.w += xe.w * xe.w;
        }
        __syncwarp();
    }
}

__global__ void __launch_bounds__(256, 4) tail_kernel(const float* __restrict__ gamma,
                                                      const float* __restrict__ beta,
                                                      float* __restrict__ out) {
    __shared__ unsigned short sIdx[8][512];    // 8 KB
    __shared__ float sWPart[8][2][CC];         // 8 KB
    __shared__ float tile[32][65];             // 8.3 KB
    __shared__ float red[2][32];

    int bx = blockIdx.x;
    int tid = threadIdx.x;
    int b = bx >> 8;
    int n0 = (bx & 255) * 16;
    int w = tid >> 5, lane = tid & 31;

    float4 ps = make_float4(0.f, 0.f, 0.f, 0.f);
    float4 ps2 = make_float4(0.f, 0.f, 0.f, 0.f);

    // phase A: E = (H@y)/deg
    agg_phase<0>(b, n0, sIdx, ps, ps2);
    grid_bar();
    // phase B: xe = y + (H@E)/deg + BN partials
    agg_phase<1>(b, n0, sIdx, ps, ps2);
    {
        sWPart[w][0][lane * 4 + 0] = ps.x;  sWPart[w][0][lane * 4 + 1] = ps.y;
        sWPart[w][0][lane * 4 + 2] = ps.z;  sWPart[w][0][lane * 4 + 3] = ps.w;
        sWPart[w][1][lane * 4 + 0] = ps2.x; sWPart[w][1][lane * 4 + 1] = ps2.y;
        sWPart[w][1][lane * 4 + 2] = ps2.z; sWPart[w][1][lane * 4 + 3] = ps2.w;
        __syncthreads();
        int c = tid & 127, which = tid >> 7;
        float s = 0.f;
        #pragma unroll
        for (int k = 0; k < 8; k++) s += sWPart[k][which][c];
        g_partT[which][c][bx] = s;
    }
    grid_bar();
    // phase C: finalize stats (blocks 0..127 = channel)
    if (bx < CC) {
        int ch = bx;
        float s = 0.f, s2 = 0.f;
        #pragma unroll
        for (int k = 0; k < 2; k++) {
            int slot = tid + k * 256;
            s  += __ldcg(&g_partT[0][ch][slot]);
            s2 += __ldcg(&g_partT[1][ch][slot]);
        }
        #pragma unroll
        for (int o = 16; o > 0; o >>= 1) {
            s  += __shfl_xor_sync(0xffffffffu, s,  o);
            s2 += __shfl_xor_sync(0xffffffffu, s2, o);
        }
        if (lane == 0) { red[0][w] = s; red[1][w] = s2; }
        __syncthreads();
        if (tid == 0) {
            float ts = 0.f, ts2 = 0.f;
            #pragma unroll
            for (int k = 0; k < 8; k++) { ts += red[0][k]; ts2 += red[1][k]; }
            float mean = ts / (float)(BB * NN);
            float var = ts2 / (float)(BB * NN) - mean * mean;
            g_mean[ch] = mean;
            g_rstd[ch] = rsqrtf(var + BN_EPS);
        }
    }
    grid_bar();
    // phase D: BN + SiLU + transpose to NCHW (32 n x 64 c per block)
    {
        int rem = bx & 255;
        int b2 = bx >> 8;
        int n0o = (rem >> 1) * 32;
        int c0o = (rem & 1) * 64;
        #pragma unroll
        for (int i = 0; i < 8; i++) {
            int idx = tid + i * 256;
            int nl = idx >> 6, cl = idx & 63;
            tile[nl][cl] = __ldcg(&g_xe[((size_t)b2 * NN + n0o + nl) * CC + c0o + cl]);
        }
        __syncthreads();
        #pragma unroll
        for (int i = 0; i < 8; i++) {
            int idx = tid + i * 256;
            int cl = idx >> 5, nl = idx & 31;
            int ch = c0o + cl;
            float v = tile[nl][cl];
            float xn = gamma[ch] * ((v - __ldcg(&g_mean[ch])) * __ldcg(&g_rstd[ch])) + beta[ch];
            float sig = 1.0f / (1.0f + expf(-xn));
            out[((size_t)b2 * CC + ch) * NN + n0o + nl] = xn * sig;
        }
    }
}

// ---------------- entry ------------------------------------------------------
extern "C" void kernel_launch(void* const* d_in, const int* in_sizes, int n_in,
                              void* d_out, int out_size) {
    const float* x     = (const float*)d_in[0];
    const float* Wfc   = (const float*)d_in[1];
    const float* bfc   = (const float*)d_in[2];
    const float* gamma = (const float*)d_in[3];
    const float* beta  = (const float*)d_in[4];
    float* out = (float*)d_out;

    void* sq_ptr = nullptr;
    cudaGetSymbolAddress(&sq_ptr, g_sq);
    cudaMemsetAsync(sq_ptr, 0, BB * NN * sizeof(float));

    cudaFuncSetAttribute(gemm_fused, cudaFuncAttributeMaxDynamicSharedMemorySize, GM_SMEM);

    prep_kernel<<<dim3(NN / 32 + 1, CC / 32, BB), dim3(32, 8)>>>(x, Wfc);
    gemm_fused<<<dim3(592, BB), 256, GM_SMEM>>>(bfc);
    tail_kernel<<<TAIL_BLOCKS, 256>>>(gamma, beta, out);
}

// round 8
// speedup vs baseline: 1.6067x; 1.0287x over previous
#include <cuda_runtime.h>
#include <cuda_bf16.h>
#include <cstdint>

#define BB 2
#define CC 128
#define NN 4096
#define THRESH2 64.0f
#define BN_EPS 1e-5f

// ---------------- scratch (device globals) -----------------------------------
__device__ __nv_bfloat16 g_xb[BB * NN * CC];
__device__ __nv_bfloat16 g_xl[BB * NN * CC];
__device__ __nv_bfloat16 g_Whi[CC * CC];
__device__ __nv_bfloat16 g_Wlo[CC * CC];
__device__ float g_sq[BB * NN];
__device__ float g_y [BB * NN * CC];
__device__ unsigned int g_Hb[(size_t)BB * NN * (NN / 32)];
__device__ float g_E [BB * NN * CC];
__device__ float g_xe[BB * NN * CC];
__device__ float g_partT[2][CC][512];
__device__ float g_mean[CC];
__device__ float g_rstd[CC];
__device__ unsigned int g_barcnt = 0;
__device__ unsigned int g_bargen = 0;

__device__ __forceinline__ uint32_t smem_u32(const void* p) {
    uint32_t a;
    asm("{ .reg .u64 t; cvta.to.shared.u64 t, %1; cvt.u32.u64 %0, t; }" : "=r"(a) : "l"(p));
    return a;
}
__device__ __forceinline__ void ldm_x4(uint32_t a[4], uint32_t addr) {
    asm volatile("ldmatrix.sync.aligned.m8n8.x4.shared.b16 {%0,%1,%2,%3}, [%4];"
                 : "=r"(a[0]), "=r"(a[1]), "=r"(a[2]), "=r"(a[3]) : "r"(addr));
}
__device__ __forceinline__ void mma16816(float c[4], const uint32_t a[4], const uint32_t b[2]) {
    asm volatile(
        "mma.sync.aligned.m16n8k16.row.col.f32.bf16.bf16.f32 "
        "{%0,%1,%2,%3}, {%4,%5,%6,%7}, {%8,%9}, {%0,%1,%2,%3};"
        : "+f"(c[0]), "+f"(c[1]), "+f"(c[2]), "+f"(c[3])
        : "r"(a[0]), "r"(a[1]), "r"(a[2]), "r"(a[3]), "r"(b[0]), "r"(b[1]));
}

// ---------------- K1: transpose + hi/lo split + sq (vector stores) -----------
// grid (NN/32 + 1, BB), block 256.  Block owns 32 n-rows x 128 channels.
__global__ void __launch_bounds__(256) prep_kernel(const float* __restrict__ x,
                                                   const float* __restrict__ Wfc) {
    int b = blockIdx.y;
    int tid = threadIdx.x;

    if (blockIdx.x == NN / 32) {               // W split: 2 blocks x 8192 elems
        int base = b * 8192;
        #pragma unroll
        for (int k = 0; k < 32; k++) {
            int i = base + tid + k * 256;
            float v = Wfc[i];
            __nv_bfloat16 h = __float2bfloat16(v);
            g_Whi[i] = h;
            g_Wlo[i] = __float2bfloat16(v - __bfloat162float(h));
        }
        return;
    }

    __shared__ float tile[32][CC + 4];         // [n][c]
    int n0 = blockIdx.x * 32;
    {
        int tx = tid & 31, ty = tid >> 5;      // tx = n offset, ty covers c
        #pragma unroll
        for (int c = 0; c < CC; c += 8)
            tile[tx][c + ty] = x[((size_t)b * CC + c + ty) * NN + n0 + tx];
    }
    __syncthreads();

    int row = tid >> 3;                        // 0..31
    int g = (tid & 7) * 16;                    // 16 channels per thread
    float s = 0.f;
    uint32_t hw[8], lw[8];
    #pragma unroll
    for (int k = 0; k < 8; k++) {
        float v0 = tile[row][g + k * 2];
        float v1 = tile[row][g + k * 2 + 1];
        s += v0 * v0 + v1 * v1;
        __nv_bfloat16 h0 = __float2bfloat16(v0);
        __nv_bfloat16 h1 = __float2bfloat16(v1);
        __nv_bfloat16 l0 = __float2bfloat16(v0 - __bfloat162float(h0));
        __nv_bfloat16 l1 = __float2bfloat16(v1 - __bfloat162float(h1));
        hw[k] = (uint32_t)__bfloat16_as_ushort(h0) | ((uint32_t)__bfloat16_as_ushort(h1) << 16);
        lw[k] = (uint32_t)__bfloat16_as_ushort(l0) | ((uint32_t)__bfloat16_as_ushort(l1) << 16);
    }
    // 8-lane reduce for sq (lanes with same row are consecutive)
    s += __shfl_xor_sync(0xffffffffu, s, 1);
    s += __shfl_xor_sync(0xffffffffu, s, 2);
    s += __shfl_xor_sync(0xffffffffu, s, 4);
    if ((tid & 7) == 0) g_sq[(size_t)b * NN + n0 + row] = s;

    size_t o = ((size_t)b * NN + n0 + row) * CC + g;
    *(uint4*)&g_xb[o]     = make_uint4(hw[0], hw[1], hw[2], hw[3]);
    *(uint4*)&g_xb[o + 8] = make_uint4(hw[4], hw[5], hw[6], hw[7]);
    *(uint4*)&g_xl[o]     = make_uint4(lw[0], lw[1], lw[2], lw[3]);
    *(uint4*)&g_xl[o + 8] = make_uint4(lw[4], lw[5], lw[6], lw[7]);
}

// ---------------- K2: fused gemm (H tiles + y tiles) -------------------------
#define HS_SQI 0
#define HS_SQJ 512
#define HS_A   1024
#define HS_B   33792
#define HS_H   66560
#define SH_STRIDE 144
#define YS_AH 0
#define YS_AL 16384
#define YS_WH 32768
#define YS_WL 65536
#define GM_SMEM 98304

__device__ void gemm_H_path(char* smem, int b, int tile_idx) {
    int tid = threadIdx.x;
    int wid = tid >> 5, lane = tid & 31;

    int idx = tile_idx, ti = 0, rem = 32;
    while (idx >= rem) { idx -= rem; ti++; rem--; }
    int tj = ti + idx;
    int n0 = ti * 128, m0 = tj * 128;

    float* sSqI = (float*)(smem + HS_SQI);
    float* sSqJ = (float*)(smem + HS_SQJ);
    if (tid < 128) {
        sSqI[tid] = g_sq[(size_t)b * NN + n0 + tid];
        sSqJ[tid] = g_sq[(size_t)b * NN + m0 + tid];
    }
    {
        const uint4* Ag = (const uint4*)(g_xb + ((size_t)b * NN + n0) * CC);
        const uint4* Bg = (const uint4*)(g_xb + ((size_t)b * NN + m0) * CC);
        #pragma unroll
        for (int it = 0; it < 8; it++) {
            int id = tid + it * 256;
            int row = id >> 4, ch = id & 15;
            int off = row * 256 + (ch ^ (row & 7)) * 16;
            *(uint4*)(smem + HS_A + off) = Ag[(size_t)row * 16 + ch];
            *(uint4*)(smem + HS_B + off) = Bg[(size_t)row * 16 + ch];
        }
    }
    __syncthreads();

    int warp_m = wid & 3, warp_n = wid >> 2;
    int mbase = warp_m * 32, nbase = warp_n * 64;

    float acc[2][8][4];
    #pragma unroll
    for (int mt = 0; mt < 2; mt++)
        #pragma unroll
        for (int nt = 0; nt < 8; nt++)
            #pragma unroll
            for (int q = 0; q < 4; q++) acc[mt][nt][q] = 0.f;

    uint32_t Abase = smem_u32(smem + HS_A);
    uint32_t Bbase = smem_u32(smem + HS_B);
    int a_row_local = lane & 15;
    int a_hi = lane >> 4;
    int bg = lane >> 3;
    int b_row_local = lane & 7;
    int b_nt_off = bg >> 1;
    int b_hi = bg & 1;

    #pragma unroll
    for (int kk = 0; kk < 8; kk++) {
        uint32_t afr[2][4];
        #pragma unroll
        for (int mt = 0; mt < 2; mt++) {
            int row = mbase + mt * 16 + a_row_local;
            int ch = (2 * kk + a_hi) ^ (row & 7);
            ldm_x4(afr[mt], Abase + row * 256 + ch * 16);
        }
        uint32_t bfr[8][2];
        #pragma unroll
        for (int nt2 = 0; nt2 < 4; nt2++) {
            int row = nbase + nt2 * 16 + b_nt_off * 8 + b_row_local;
            int ch = (2 * kk + b_hi) ^ (row & 7);
            uint32_t r4[4];
            ldm_x4(r4, Bbase + row * 256 + ch * 16);
            bfr[nt2 * 2][0] = r4[0]; bfr[nt2 * 2][1] = r4[1];
            bfr[nt2 * 2 + 1][0] = r4[2]; bfr[nt2 * 2 + 1][1] = r4[3];
        }
        #pragma unroll
        for (int mt = 0; mt < 2; mt++)
            #pragma unroll
            for (int nt = 0; nt < 8; nt++)
                mma16816(acc[mt][nt], afr[mt], bfr[nt]);
    }

    unsigned char* sH = (unsigned char*)(smem + HS_H);
    int rrow = lane >> 2;
    int ccol = (lane & 3) * 2;
    #pragma unroll
    for (int mt = 0; mt < 2; mt++) {
        #pragma unroll
        for (int nt = 0; nt < 8; nt++) {
            int col = nbase + nt * 8 + ccol;
            float sm0 = sSqJ[col], sm1 = sSqJ[col + 1];
            #pragma unroll
            for (int h = 0; h < 2; h++) {
                int row = mbase + mt * 16 + rrow + h * 8;
                float sqn = sSqI[row];
                float d20 = sqn + sm0 - 2.0f * acc[mt][nt][h * 2 + 0];
                float d21 = sqn + sm1 - 2.0f * acc[mt][nt][h * 2 + 1];
                sH[row * SH_STRIDE + col]     = (d20 < THRESH2) ? 1 : 0;
                sH[row * SH_STRIDE + col + 1] = (d21 < THRESH2) ? 1 : 0;
            }
        }
    }
    __syncthreads();

    unsigned int* Hb = g_Hb + (size_t)b * NN * (NN / 32);
    #pragma unroll
    for (int it = 0; it < 2; it++) {
        int id = tid + it * 256;
        int row = id >> 2, w = id & 3;
        const unsigned int* src = (const unsigned int*)(sH + row * SH_STRIDE + w * 32);
        unsigned int bits = 0;
        #pragma unroll
        for (int k = 0; k < 8; k++) {
            unsigned int u = src[k];
            bits |= (u & 1u) << (k * 4);
            bits |= ((u >> 8) & 1u) << (k * 4 + 1);
            bits |= ((u >> 16) & 1u) << (k * 4 + 2);
            bits |= ((u >> 24) & 1u) << (k * 4 + 3);
        }
        Hb[(size_t)(n0 + row) * (NN / 32) + (m0 >> 5) + w] = bits;
    }
    if (ti != tj && tid < 128) {
        int mrow = tid;
        unsigned int wbits[4];
        #pragma unroll
        for (int w = 0; w < 4; w++) {
            unsigned int bits = 0;
            #pragma unroll
            for (int q = 0; q < 32; q++)
                bits |= (unsigned int)(sH[(w * 32 + q) * SH_STRIDE + mrow] & 1u) << q;
            wbits[w] = bits;
        }
        *(uint4*)&Hb[(size_t)(m0 + mrow) * (NN / 32) + (n0 >> 5)] =
            make_uint4(wbits[0], wbits[1], wbits[2], wbits[3]);
    }
}

__device__ void gemm_y_path(char* smem, int b, int ytile, const float* __restrict__ bfc) {
    int tid = threadIdx.x;
    int wid = tid >> 5, lane = tid & 31;
    int n0 = ytile * 64;

    {
        const uint4* Ah = (const uint4*)(g_xb + ((size_t)b * NN + n0) * CC);
        const uint4* Al = (const uint4*)(g_xl + ((size_t)b * NN + n0) * CC);
        #pragma unroll
        for (int it = 0; it < 4; it++) {
            int id = tid + it * 256;
            int row = id >> 4, ch = id & 15;
            int off = row * 256 + (ch ^ (row & 7)) * 16;
            *(uint4*)(smem + YS_AH + off) = Ah[(size_t)row * 16 + ch];
            *(uint4*)(smem + YS_AL + off) = Al[(size_t)row * 16 + ch];
        }
        const uint4* Wh = (const uint4*)g_Whi;
        const uint4* Wl = (const uint4*)g_Wlo;
        #pragma unroll
        for (int it = 0; it < 8; it++) {
            int id = tid + it * 256;
            int row = id >> 4, ch = id & 15;
            int off = row * 256 + (ch ^ (row & 7)) * 16;
            *(uint4*)(smem + YS_WH + off) = Wh[(size_t)row * 16 + ch];
            *(uint4*)(smem + YS_WL + off) = Wl[(size_t)row * 16 + ch];
        }
    }
    __syncthreads();

    int warp_m = wid & 1, warp_n = wid >> 1;
    int mbase = warp_m * 32, nbase = warp_n * 32;

    float acc[2][4][4];
    #pragma unroll
    for (int mt = 0; mt < 2; mt++)
        #pragma unroll
        for (int nt = 0; nt < 4; nt++)
            #pragma unroll
            for (int q = 0; q < 4; q++) acc[mt][nt][q] = 0.f;

    int a_row_local = lane & 15;
    int a_hi = lane >> 4;
    int bg = lane >> 3;
    int b_row_local = lane & 7;
    int b_nt_off = bg >> 1;
    int b_hi = bg & 1;

    #pragma unroll
    for (int pass = 0; pass < 3; pass++) {
        uint32_t Abase = smem_u32(smem + (pass == 2 ? YS_AL : YS_AH));
        uint32_t Bbase = smem_u32(smem + (pass == 1 ? YS_WL : YS_WH));
        #pragma unroll
        for (int kk = 0; kk < 8; kk++) {
            uint32_t afr[2][4];
            #pragma unroll
            for (int mt = 0; mt < 2; mt++) {
                int row = mbase + mt * 16 + a_row_local;
                int ch = (2 * kk + a_hi) ^ (row & 7);
                ldm_x4(afr[mt], Abase + row * 256 + ch * 16);
            }
            uint32_t bfr[4][2];
            #pragma unroll
            for (int nt2 = 0; nt2 < 2; nt2++) {
                int row = nbase + nt2 * 16 + b_nt_off * 8 + b_row_local;
                int ch = (2 * kk + b_hi) ^ (row & 7);
                uint32_t r4[4];
                ldm_x4(r4, Bbase + row * 256 + ch * 16);
                bfr[nt2 * 2][0] = r4[0]; bfr[nt2 * 2][1] = r4[1];
                bfr[nt2 * 2 + 1][0] = r4[2]; bfr[nt2 * 2 + 1][1] = r4[3];
            }
            #pragma unroll
            for (int mt = 0; mt < 2; mt++)
                #pragma unroll
                for (int nt = 0; nt < 4; nt++)
                    mma16816(acc[mt][nt], afr[mt], bfr[nt]);
        }
    }

    int rrow = lane >> 2;
    int ccol = (lane & 3) * 2;
    float* Y = g_y + ((size_t)b * NN + n0) * CC;
    #pragma unroll
    for (int mt = 0; mt < 2; mt++) {
        #pragma unroll
        for (int nt = 0; nt < 4; nt++) {
            int col = nbase + nt * 8 + ccol;
            float b0 = bfc[col], b1 = bfc[col + 1];
            #pragma unroll
            for (int h = 0; h < 2; h++) {
                int row = mbase + mt * 16 + rrow + h * 8;
                Y[(size_t)row * CC + col]     = acc[mt][nt][h * 2 + 0] + b0;
                Y[(size_t)row * CC + col + 1] = acc[mt][nt][h * 2 + 1] + b1;
            }
        }
    }
}

__global__ void __launch_bounds__(256, 2) gemm_fused(const float* __restrict__ bfc) {
    extern __shared__ char smem[];
    int b = blockIdx.y;
    if (blockIdx.x < 528) gemm_H_path(smem, b, blockIdx.x);
    else                  gemm_y_path(smem, b, blockIdx.x - 528, bfc);
}

// ---------------- K3: mega tail ---------------------------------------------
#define TAIL_BLOCKS 512

__device__ __forceinline__ void grid_bar() {
    __syncthreads();
    if (threadIdx.x == 0) {
        __threadfence();
        unsigned int gen = *((volatile unsigned int*)&g_bargen);
        if (atomicAdd(&g_barcnt, 1u) == TAIL_BLOCKS - 1) {
            g_barcnt = 0;
            __threadfence();
            *((volatile unsigned int*)&g_bargen) = gen + 1;
        } else {
            while (*((volatile unsigned int*)&g_bargen) == gen) __nanosleep(64);
        }
    }
    __syncthreads();
}

// warp-per-row aggregation, 2 rows per warp processed CONCURRENTLY.
template <int MODE>
__device__ void agg_phase(int b, int n0, unsigned short (*sIdx)[2][512],
                          float4& ps, float4& ps2) {
    int tid = threadIdx.x;
    int w = tid >> 5, lane = tid & 31;
    const float* S = (MODE == 0 ? g_y : g_E) + (size_t)b * NN * CC;
    const float* Yb = g_y + (size_t)b * NN * CC;
    const float* Scol = S + lane * 4;

    int n1 = n0 + w, n2 = n0 + 8 + w;
    const unsigned int* Hrow1 = g_Hb + ((size_t)b * NN + n1) * (NN / 32);
    const unsigned int* Hrow2 = g_Hb + ((size_t)b * NN + n2) * (NN / 32);
    uint4 wv1 = ((const uint4*)Hrow1)[lane];
    uint4 wv2 = ((const uint4*)Hrow2)[lane];

    int cnt1 = __popc(wv1.x) + __popc(wv1.y) + __popc(wv1.z) + __popc(wv1.w);
    int cnt2 = __popc(wv2.x) + __popc(wv2.y) + __popc(wv2.z) + __popc(wv2.w);
    int pre1 = cnt1, pre2 = cnt2;
    #pragma unroll
    for (int o = 1; o < 32; o <<= 1) {
        int t1 = __shfl_up_sync(0xffffffffu, pre1, o);
        int t2 = __shfl_up_sync(0xffffffffu, pre2, o);
        if (lane >= o) { pre1 += t1; pre2 += t2; }
    }
    int deg1 = __shfl_sync(0xffffffffu, pre1, 31);
    int deg2 = __shfl_sync(0xffffffffu, pre2, 31);

    float4 acc1 = make_float4(0.f, 0.f, 0.f, 0.f);
    float4 acc2 = make_float4(0.f, 0.f, 0.f, 0.f);

    bool fast = (deg1 <= 512) && (deg2 <= 512);
    if (fast) {
        {
            int kpos = pre1 - cnt1;
            unsigned int arr[4] = {wv1.x, wv1.y, wv1.z, wv1.w};
            #pragma unroll
            for (int j = 0; j < 4; j++) {
                unsigned int bits = arr[j];
                while (bits) {
                    int q = __ffs(bits) - 1;
                    bits &= bits - 1;
                    sIdx[w][0][kpos++] = (unsigned short)(lane * 128 + j * 32 + q);
                }
            }
        }
        {
            int kpos = pre2 - cnt2;
            unsigned int arr[4] = {wv2.x, wv2.y, wv2.z, wv2.w};
            #pragma unroll
            for (int j = 0; j < 4; j++) {
                unsigned int bits = arr[j];
                while (bits) {
                    int q = __ffs(bits) - 1;
                    bits &= bits - 1;
                    sIdx[w][1][kpos++] = (unsigned short)(lane * 128 + j * 32 + q);
                }
            }
        }
        __syncwarp();
        int dmax = (deg1 > deg2) ? deg1 : deg2;
        for (int ii = 0; ii < dmax; ii++) {
            if (ii < deg1) {
                int m = sIdx[w][0][ii];
                float4 v = (MODE == 0)
                    ? *(const float4*)(Scol + (size_t)m * CC)
                    : __ldcg((const float4*)(Scol + (size_t)m * CC));
                acc1.x += v.x; acc1.y += v.y; acc1.z += v.z; acc1.w += v.w;
            }
            if (ii < deg2) {
                int m = sIdx[w][1][ii];
                float4 v = (MODE == 0)
                    ? *(const float4*)(Scol + (size_t)m * CC)
                    : __ldcg((const float4*)(Scol + (size_t)m * CC));
                acc2.x += v.x; acc2.y += v.y; acc2.z += v.z; acc2.w += v.w;
            }
        }
    } else {
        for (int w2 = 0; w2 < NN / 32; w2++) {
            unsigned int bits = Hrow1[w2];
            while (bits) {
                int q = __ffs(bits) - 1; bits &= bits - 1;
                int m = w2 * 32 + q;
                float4 v = (MODE == 0)
                    ? *(const float4*)(Scol + (size_t)m * CC)
                    : __ldcg((const float4*)(Scol + (size_t)m * CC));
                acc1.x += v.x; acc1.y += v.y; acc1.z += v.z; acc1.w += v.w;
            }
            bits = Hrow2[w2];
            while (bits) {
                int q = __ffs(bits) - 1; bits &= bits - 1;
                int m = w2 * 32 + q;
                float4 v = (MODE == 0)
                    ? *(const float4*)(Scol + (size_t)m * CC)
                    : __ldcg((const float4*)(Scol + (size_t)m * CC));
                acc2.x += v.x; acc2.y += v.y; acc2.z += v.z; acc2.w += v.w;
            }
        }
    }

    float inv1 = (deg1 > 0) ? (1.0f / (float)deg1) : 0.0f;
    float inv2 = (deg2 > 0) ? (1.0f / (float)deg2) : 0.0f;
    float4 vo1 = make_float4(acc1.x * inv1, acc1.y * inv1, acc1.z * inv1, acc1.w * inv1);
    float4 vo2 = make_float4(acc2.x * inv2, acc2.y * inv2, acc2.z * inv2, acc2.w * inv2);
    size_t o1 = ((size_t)b * NN + n1) * CC + lane * 4;
    size_t o2 = ((size_t)b * NN + n2) * CC + lane * 4;
    if (MODE == 0) {
        *(float4*)&g_E[o1] = vo1;
        *(float4*)&g_E[o2] = vo2;
    } else {
        float4 y1 = *(const float4*)(Yb + (size_t)n1 * CC + lane * 4);
        float4 y2 = *(const float4*)(Yb + (size_t)n2 * CC + lane * 4);
        float4 xe1 = make_float4(y1.x + vo1.x, y1.y + vo1.y, y1.z + vo1.z, y1.w + vo1.w);
        float4 xe2 = make_float4(y2.x + vo2.x, y2.y + vo2.y, y2.z + vo2.z, y2.w + vo2.w);
        *(float4*)&g_xe[o1] = xe1;
        *(float4*)&g_xe[o2] = xe2;
        ps.x += xe1.x + xe2.x; ps.y += xe1.y + xe2.y;
        ps.z += xe1.z + xe2.z; ps.w += xe1.w + xe2.w;
        ps2.x += xe1.x * xe1.x + xe2.x * xe2.x;
        ps2.y += xe1.y * xe1.y + xe2.y * xe2.y;
        ps2.z += xe1.z * xe1.z + xe2.z * xe2.z;
        ps2.w += xe1.w * xe1.w + xe2.w * xe2.w;
    }
    __syncwarp();
}

__global__ void __launch_bounds__(256, 4) tail_kernel(const float* __restrict__ gamma,
                                                      const float* __restrict__ beta,
                                                      float* __restrict__ out) {
    __shared__ unsigned short sIdx[8][2][512];   // 16 KB
    __shared__ float sWPart[8][2][CC];           // 8 KB
    __shared__ float tile[32][65];               // 8.3 KB
    __shared__ float red[2][32];

    int bx = blockIdx.x;
    int tid = threadIdx.x;
    int b = bx >> 8;
    int n0 = (bx & 255) * 16;
    int w = tid >> 5, lane = tid & 31;

    float4 ps = make_float4(0.f, 0.f, 0.f, 0.f);
    float4 ps2 = make_float4(0.f, 0.f, 0.f, 0.f);

    agg_phase<0>(b, n0, sIdx, ps, ps2);
    grid_bar();
    agg_phase<1>(b, n0, sIdx, ps, ps2);
    {
        sWPart[w][0][lane * 4 + 0] = ps.x;  sWPart[w][0][lane * 4 + 1] = ps.y;
        sWPart[w][0][lane * 4 + 2] = ps.z;  sWPart[w][0][lane * 4 + 3] = ps.w;
        sWPart[w][1][lane * 4 + 0] = ps2.x; sWPart[w][1][lane * 4 + 1] = ps2.y;
        sWPart[w][1][lane * 4 + 2] = ps2.z; sWPart[w][1][lane * 4 + 3] = ps2.w;
        __syncthreads();
        int c = tid & 127, which = tid >> 7;
        float s = 0.f;
        #pragma unroll
        for (int k = 0; k < 8; k++) s += sWPart[k][which][c];
        g_partT[which][c][bx] = s;
    }
    grid_bar();
    if (bx < CC) {
        int ch = bx;
        float s = 0.f, s2 = 0.f;
        #pragma unroll
        for (int k = 0; k < 2; k++) {
            int slot = tid + k * 256;
            s  += __ldcg(&g_partT[0][ch][slot]);
            s2 += __ldcg(&g_partT[1][ch][slot]);
        }
        #pragma unroll
        for (int o = 16; o > 0; o >>= 1) {
            s  += __shfl_xor_sync(0xffffffffu, s,  o);
            s2 += __shfl_xor_sync(0xffffffffu, s2, o);
        }
        if (lane == 0) { red[0][w] = s; red[1][w] = s2; }
        __syncthreads();
        if (tid == 0) {
            float ts = 0.f, ts2 = 0.f;
            #pragma unroll
            for (int k = 0; k < 8; k++) { ts += red[0][k]; ts2 += red[1][k]; }
            float mean = ts / (float)(BB * NN);
            float var = ts2 / (float)(BB * NN) - mean * mean;
            g_mean[ch] = mean;
            g_rstd[ch] = rsqrtf(var + BN_EPS);
        }
    }
    grid_bar();
    {
        int rem = bx & 255;
        int b2 = bx >> 8;
        int n0o = (rem >> 1) * 32;
        int c0o = (rem & 1) * 64;
        #pragma unroll
        for (int i = 0; i < 8; i++) {
            int idx = tid + i * 256;
            int nl = idx >> 6, cl = idx & 63;
            tile[nl][cl] = __ldcg(&g_xe[((size_t)b2 * NN + n0o + nl) * CC + c0o + cl]);
        }
        __syncthreads();
        #pragma unroll
        for (int i = 0; i < 8; i++) {
            int idx = tid + i * 256;
            int cl = idx >> 5, nl = idx & 31;
            int ch = c0o + cl;
            float v = tile[nl][cl];
            float xn = gamma[ch] * ((v - __ldcg(&g_mean[ch])) * __ldcg(&g_rstd[ch])) + beta[ch];
            float sig = 1.0f / (1.0f + expf(-xn));
            out[((size_t)b2 * CC + ch) * NN + n0o + nl] = xn * sig;
        }
    }
}

// ---------------- entry ------------------------------------------------------
extern "C" void kernel_launch(void* const* d_in, const int* in_sizes, int n_in,
                              void* d_out, int out_size) {
    const float* x     = (const float*)d_in[0];
    const float* Wfc   = (const float*)d_in[1];
    const float* bfc   = (const float*)d_in[2];
    const float* gamma = (const float*)d_in[3];
    const float* beta  = (const float*)d_in[4];
    float* out = (float*)d_out;

    cudaFuncSetAttribute(gemm_fused, cudaFuncAttributeMaxDynamicSharedMemorySize, GM_SMEM);

    prep_kernel<<<dim3(NN / 32 + 1, BB), 256>>>(x, Wfc);
    gemm_fused<<<dim3(592, BB), 256, GM_SMEM>>>(bfc);
    tail_kernel<<<TAIL_BLOCKS, 256>>>(gamma, beta, out);
}

// round 9
// speedup vs baseline: 1.8856x; 1.1736x over previous
#include <cuda_runtime.h>
#include <cuda_bf16.h>
#include <cstdint>

#define BB 2
#define CC 128
#define NN 4096
#define THRESH2 64.0f
#define BN_EPS 1e-5f

// ---------------- scratch (device globals) -----------------------------------
__device__ __nv_bfloat16 g_xb[BB * NN * CC];
__device__ __nv_bfloat16 g_xl[BB * NN * CC];
__device__ __nv_bfloat16 g_Whi[CC * CC];
__device__ __nv_bfloat16 g_Wlo[CC * CC];
__device__ float g_sqp[2][BB * NN];                   // per-channel-half sq partials
__device__ float g_y [BB * NN * CC];
__device__ unsigned int g_Hb[(size_t)BB * NN * (NN / 32)];
__device__ float g_E [BB * NN * CC];
__device__ float g_partT[2][CC][512];
__device__ float g_mean[CC];
__device__ float g_rstd[CC];
__device__ unsigned int g_barcnt = 0;
__device__ unsigned int g_bargen = 0;

__device__ __forceinline__ uint32_t smem_u32(const void* p) {
    uint32_t a;
    asm("{ .reg .u64 t; cvta.to.shared.u64 t, %1; cvt.u32.u64 %0, t; }" : "=r"(a) : "l"(p));
    return a;
}
__device__ __forceinline__ void ldm_x4(uint32_t a[4], uint32_t addr) {
    asm volatile("ldmatrix.sync.aligned.m8n8.x4.shared.b16 {%0,%1,%2,%3}, [%4];"
                 : "=r"(a[0]), "=r"(a[1]), "=r"(a[2]), "=r"(a[3]) : "r"(addr));
}
__device__ __forceinline__ void mma16816(float c[4], const uint32_t a[4], const uint32_t b[2]) {
    asm volatile(
        "mma.sync.aligned.m16n8k16.row.col.f32.bf16.bf16.f32 "
        "{%0,%1,%2,%3}, {%4,%5,%6,%7}, {%8,%9}, {%0,%1,%2,%3};"
        : "+f"(c[0]), "+f"(c[1]), "+f"(c[2]), "+f"(c[3])
        : "r"(a[0]), "r"(a[1]), "r"(a[2]), "r"(a[3]), "r"(b[0]), "r"(b[1]));
}

// ---------------- K1: transpose + hi/lo split + sq partials ------------------
// grid (129, 2, BB), block 256.  Tile blocks own 32 n x 64 c (y = channel half).
__global__ void __launch_bounds__(256) prep_kernel(const float* __restrict__ x,
                                                   const float* __restrict__ Wfc) {
    int b = blockIdx.z;
    int ch = blockIdx.y;                       // channel half
    int tid = threadIdx.x;

    if (blockIdx.x == NN / 32) {               // W split: 4 blocks x 4096 elems
        int base = (b * 2 + ch) * 4096;
        #pragma unroll
        for (int k = 0; k < 16; k++) {
            int i = base + tid + k * 256;
            float v = Wfc[i];
            __nv_bfloat16 h = __float2bfloat16(v);
            g_Whi[i] = h;
            g_Wlo[i] = __float2bfloat16(v - __bfloat162float(h));
        }
        return;
    }

    __shared__ float tile[32][65];             // [n][c_local]
    int n0 = blockIdx.x * 32;
    int c0 = ch * 64;
    {
        int c_local = tid >> 2, f = tid & 3;   // 64 rows, 4 threads each
        const float* src = x + ((size_t)b * CC + c0 + c_local) * NN + n0;
        #pragma unroll
        for (int j = 0; j < 2; j++) {
            int noff = (f * 2 + j) * 4;
            float4 v = *(const float4*)(src + noff);
            tile[noff + 0][c_local] = v.x;
            tile[noff + 1][c_local] = v.y;
            tile[noff + 2][c_local] = v.z;
            tile[noff + 3][c_local] = v.w;
        }
    }
    __syncthreads();

    int row = tid >> 3;                        // 0..31
    int g = (tid & 7) * 8;                     // 8 channels of this half
    float s = 0.f;
    uint32_t hw[4], lw[4];
    #pragma unroll
    for (int k = 0; k < 4; k++) {
        float v0 = tile[row][g + k * 2];
        float v1 = tile[row][g + k * 2 + 1];
        s += v0 * v0 + v1 * v1;
        __nv_bfloat16 h0 = __float2bfloat16(v0);
        __nv_bfloat16 h1 = __float2bfloat16(v1);
        __nv_bfloat16 l0 = __float2bfloat16(v0 - __bfloat162float(h0));
        __nv_bfloat16 l1 = __float2bfloat16(v1 - __bfloat162float(h1));
        hw[k] = (uint32_t)__bfloat16_as_ushort(h0) | ((uint32_t)__bfloat16_as_ushort(h1) << 16);
        lw[k] = (uint32_t)__bfloat16_as_ushort(l0) | ((uint32_t)__bfloat16_as_ushort(l1) << 16);
    }
    s += __shfl_xor_sync(0xffffffffu, s, 1);
    s += __shfl_xor_sync(0xffffffffu, s, 2);
    s += __shfl_xor_sync(0xffffffffu, s, 4);
    if ((tid & 7) == 0) g_sqp[ch][(size_t)b * NN + n0 + row] = s;

    size_t o = ((size_t)b * NN + n0 + row) * CC + c0 + g;
    *(uint4*)&g_xb[o] = make_uint4(hw[0], hw[1], hw[2], hw[3]);
    *(uint4*)&g_xl[o] = make_uint4(lw[0], lw[1], lw[2], lw[3]);
}

// ---------------- K2: fused gemm (H tiles + y tiles) -------------------------
#define HS_SQI 0
#define HS_SQJ 512
#define HS_A   1024
#define HS_B   33792
#define HS_H   66560
#define SH_STRIDE 144
#define YS_AH 0
#define YS_AL 16384
#define YS_WH 32768
#define YS_WL 65536
#define GM_SMEM 98304

__device__ void gemm_H_path(char* smem, int b, int tile_idx) {
    int tid = threadIdx.x;
    int wid = tid >> 5, lane = tid & 31;

    int idx = tile_idx, ti = 0, rem = 32;
    while (idx >= rem) { idx -= rem; ti++; rem--; }
    int tj = ti + idx;
    int n0 = ti * 128, m0 = tj * 128;

    float* sSqI = (float*)(smem + HS_SQI);
    float* sSqJ = (float*)(smem + HS_SQJ);
    if (tid < 128) {
        sSqI[tid] = g_sqp[0][(size_t)b * NN + n0 + tid] + g_sqp[1][(size_t)b * NN + n0 + tid];
        sSqJ[tid] = g_sqp[0][(size_t)b * NN + m0 + tid] + g_sqp[1][(size_t)b * NN + m0 + tid];
    }
    {
        const uint4* Ag = (const uint4*)(g_xb + ((size_t)b * NN + n0) * CC);
        const uint4* Bg = (const uint4*)(g_xb + ((size_t)b * NN + m0) * CC);
        #pragma unroll
        for (int it = 0; it < 8; it++) {
            int id = tid + it * 256;
            int row = id >> 4, ch = id & 15;
            int off = row * 256 + (ch ^ (row & 7)) * 16;
            *(uint4*)(smem + HS_A + off) = Ag[(size_t)row * 16 + ch];
            *(uint4*)(smem + HS_B + off) = Bg[(size_t)row * 16 + ch];
        }
    }
    __syncthreads();

    int warp_m = wid & 3, warp_n = wid >> 2;
    int mbase = warp_m * 32, nbase = warp_n * 64;

    float acc[2][8][4];
    #pragma unroll
    for (int mt = 0; mt < 2; mt++)
        #pragma unroll
        for (int nt = 0; nt < 8; nt++)
            #pragma unroll
            for (int q = 0; q < 4; q++) acc[mt][nt][q] = 0.f;

    uint32_t Abase = smem_u32(smem + HS_A);
    uint32_t Bbase = smem_u32(smem + HS_B);
    int a_row_local = lane & 15;
    int a_hi = lane >> 4;
    int bg = lane >> 3;
    int b_row_local = lane & 7;
    int b_nt_off = bg >> 1;
    int b_hi = bg & 1;

    #pragma unroll
    for (int kk = 0; kk < 8; kk++) {
        uint32_t afr[2][4];
        #pragma unroll
        for (int mt = 0; mt < 2; mt++) {
            int row = mbase + mt * 16 + a_row_local;
            int ch = (2 * kk + a_hi) ^ (row & 7);
            ldm_x4(afr[mt], Abase + row * 256 + ch * 16);
        }
        uint32_t bfr[8][2];
        #pragma unroll
        for (int nt2 = 0; nt2 < 4; nt2++) {
            int row = nbase + nt2 * 16 + b_nt_off * 8 + b_row_local;
            int ch = (2 * kk + b_hi) ^ (row & 7);
            uint32_t r4[4];
            ldm_x4(r4, Bbase + row * 256 + ch * 16);
            bfr[nt2 * 2][0] = r4[0]; bfr[nt2 * 2][1] = r4[1];
            bfr[nt2 * 2 + 1][0] = r4[2]; bfr[nt2 * 2 + 1][1] = r4[3];
        }
        #pragma unroll
        for (int mt = 0; mt < 2; mt++)
            #pragma unroll
            for (int nt = 0; nt < 8; nt++)
                mma16816(acc[mt][nt], afr[mt], bfr[nt]);
    }

    unsigned char* sH = (unsigned char*)(smem + HS_H);
    int rrow = lane >> 2;
    int ccol = (lane & 3) * 2;
    #pragma unroll
    for (int mt = 0; mt < 2; mt++) {
        #pragma unroll
        for (int nt = 0; nt < 8; nt++) {
            int col = nbase + nt * 8 + ccol;
            float sm0 = sSqJ[col], sm1 = sSqJ[col + 1];
            #pragma unroll
            for (int h = 0; h < 2; h++) {
                int row = mbase + mt * 16 + rrow + h * 8;
                float sqn = sSqI[row];
                float d20 = sqn + sm0 - 2.0f * acc[mt][nt][h * 2 + 0];
                float d21 = sqn + sm1 - 2.0f * acc[mt][nt][h * 2 + 1];
                sH[row * SH_STRIDE + col]     = (d20 < THRESH2) ? 1 : 0;
                sH[row * SH_STRIDE + col + 1] = (d21 < THRESH2) ? 1 : 0;
            }
        }
    }
    __syncthreads();

    unsigned int* Hb = g_Hb + (size_t)b * NN * (NN / 32);
    #pragma unroll
    for (int it = 0; it < 2; it++) {
        int id = tid + it * 256;
        int row = id >> 2, w = id & 3;
        const unsigned int* src = (const unsigned int*)(sH + row * SH_STRIDE + w * 32);
        unsigned int bits = 0;
        #pragma unroll
        for (int k = 0; k < 8; k++) {
            unsigned int u = src[k];
            bits |= (u & 1u) << (k * 4);
            bits |= ((u >> 8) & 1u) << (k * 4 + 1);
            bits |= ((u >> 16) & 1u) << (k * 4 + 2);
            bits |= ((u >> 24) & 1u) << (k * 4 + 3);
        }
        Hb[(size_t)(n0 + row) * (NN / 32) + (m0 >> 5) + w] = bits;
    }
    if (ti != tj && tid < 128) {
        int mrow = tid;
        unsigned int wbits[4];
        #pragma unroll
        for (int w = 0; w < 4; w++) {
            unsigned int bits = 0;
            #pragma unroll
            for (int q = 0; q < 32; q++)
                bits |= (unsigned int)(sH[(w * 32 + q) * SH_STRIDE + mrow] & 1u) << q;
            wbits[w] = bits;
        }
        *(uint4*)&Hb[(size_t)(m0 + mrow) * (NN / 32) + (n0 >> 5)] =
            make_uint4(wbits[0], wbits[1], wbits[2], wbits[3]);
    }
}

__device__ void gemm_y_path(char* smem, int b, int ytile, const float* __restrict__ bfc) {
    int tid = threadIdx.x;
    int wid = tid >> 5, lane = tid & 31;
    int n0 = ytile * 64;

    {
        const uint4* Ah = (const uint4*)(g_xb + ((size_t)b * NN + n0) * CC);
        const uint4* Al = (const uint4*)(g_xl + ((size_t)b * NN + n0) * CC);
        #pragma unroll
        for (int it = 0; it < 4; it++) {
            int id = tid + it * 256;
            int row = id >> 4, ch = id & 15;
            int off = row * 256 + (ch ^ (row & 7)) * 16;
            *(uint4*)(smem + YS_AH + off) = Ah[(size_t)row * 16 + ch];
            *(uint4*)(smem + YS_AL + off) = Al[(size_t)row * 16 + ch];
        }
        const uint4* Wh = (const uint4*)g_Whi;
        const uint4* Wl = (const uint4*)g_Wlo;
        #pragma unroll
        for (int it = 0; it < 8; it++) {
            int id = tid + it * 256;
            int row = id >> 4, ch = id & 15;
            int off = row * 256 + (ch ^ (row & 7)) * 16;
            *(uint4*)(smem + YS_WH + off) = Wh[(size_t)row * 16 + ch];
            *(uint4*)(smem + YS_WL + off) = Wl[(size_t)row * 16 + ch];
        }
    }
    __syncthreads();

    int warp_m = wid & 1, warp_n = wid >> 1;
    int mbase = warp_m * 32, nbase = warp_n * 32;

    float acc[2][4][4];
    #pragma unroll
    for (int mt = 0; mt < 2; mt++)
        #pragma unroll
        for (int nt = 0; nt < 4; nt++)
            #pragma unroll
            for (int q = 0; q < 4; q++) acc[mt][nt][q] = 0.f;

    int a_row_local = lane & 15;
    int a_hi = lane >> 4;
    int bg = lane >> 3;
    int b_row_local = lane & 7;
    int b_nt_off = bg >> 1;
    int b_hi = bg & 1;

    #pragma unroll
    for (int pass = 0; pass < 3; pass++) {
        uint32_t Abase = smem_u32(smem + (pass == 2 ? YS_AL : YS_AH));
        uint32_t Bbase = smem_u32(smem + (pass == 1 ? YS_WL : YS_WH));
        #pragma unroll
        for (int kk = 0; kk < 8; kk++) {
            uint32_t afr[2][4];
            #pragma unroll
            for (int mt = 0; mt < 2; mt++) {
                int row = mbase + mt * 16 + a_row_local;
                int ch = (2 * kk + a_hi) ^ (row & 7);
                ldm_x4(afr[mt], Abase + row * 256 + ch * 16);
            }
            uint32_t bfr[4][2];
            #pragma unroll
            for (int nt2 = 0; nt2 < 2; nt2++) {
                int row = nbase + nt2 * 16 + b_nt_off * 8 + b_row_local;
                int ch = (2 * kk + b_hi) ^ (row & 7);
                uint32_t r4[4];
                ldm_x4(r4, Bbase + row * 256 + ch * 16);
                bfr[nt2 * 2][0] = r4[0]; bfr[nt2 * 2][1] = r4[1];
                bfr[nt2 * 2 + 1][0] = r4[2]; bfr[nt2 * 2 + 1][1] = r4[3];
            }
            #pragma unroll
            for (int mt = 0; mt < 2; mt++)
                #pragma unroll
                for (int nt = 0; nt < 4; nt++)
                    mma16816(acc[mt][nt], afr[mt], bfr[nt]);
        }
    }

    int rrow = lane >> 2;
    int ccol = (lane & 3) * 2;
    float* Y = g_y + ((size_t)b * NN + n0) * CC;
    #pragma unroll
    for (int mt = 0; mt < 2; mt++) {
        #pragma unroll
        for (int nt = 0; nt < 4; nt++) {
            int col = nbase + nt * 8 + ccol;
            float b0 = bfc[col], b1 = bfc[col + 1];
            #pragma unroll
            for (int h = 0; h < 2; h++) {
                int row = mbase + mt * 16 + rrow + h * 8;
                Y[(size_t)row * CC + col]     = acc[mt][nt][h * 2 + 0] + b0;
                Y[(size_t)row * CC + col + 1] = acc[mt][nt][h * 2 + 1] + b1;
            }
        }
    }
}

__global__ void __launch_bounds__(256, 2) gemm_fused(const float* __restrict__ bfc) {
    extern __shared__ char smem[];
    int b = blockIdx.y;
    if (blockIdx.x < 528) gemm_H_path(smem, b, blockIdx.x);
    else                  gemm_y_path(smem, b, blockIdx.x - 528, bfc);
}

// ---------------- K3: mega tail ---------------------------------------------
#define TAIL_BLOCKS 512

__device__ __forceinline__ void grid_bar() {
    __syncthreads();
    if (threadIdx.x == 0) {
        __threadfence();
        unsigned int gen = *((volatile unsigned int*)&g_bargen);
        if (atomicAdd(&g_barcnt, 1u) == TAIL_BLOCKS - 1) {
            g_barcnt = 0;
            __threadfence();
            *((volatile unsigned int*)&g_bargen) = gen + 1;
        } else {
            while (*((volatile unsigned int*)&g_bargen) == gen) __nanosleep(64);
        }
    }
    __syncthreads();
}

// gather two rows using precomputed compaction.  MODE 0: y -> E (global).
// MODE 1: E -> xe (smem) + BN partials.
template <int MODE>
__device__ void gather2(int b, int n1, int n2, int deg1, int deg2, bool fast,
                        const unsigned int* Hrow1, const unsigned int* Hrow2,
                        unsigned short (*sIdx)[2][512], float (*sXe)[CC + 4],
                        int w, int lane, float4& ps, float4& ps2) {
    const float* S = (MODE == 0 ? g_y : g_E) + (size_t)b * NN * CC;
    const float* Scol = S + lane * 4;
    float4 acc1 = make_float4(0.f, 0.f, 0.f, 0.f);
    float4 acc2 = make_float4(0.f, 0.f, 0.f, 0.f);

    if (fast) {
        int dmax = (deg1 > deg2) ? deg1 : deg2;
        for (int ii = 0; ii < dmax; ii++) {
            if (ii < deg1) {
                int m = sIdx[w][0][ii];
                float4 v = (MODE == 0)
                    ? *(const float4*)(Scol + (size_t)m * CC)
                    : __ldcg((const float4*)(Scol + (size_t)m * CC));
                acc1.x += v.x; acc1.y += v.y; acc1.z += v.z; acc1.w += v.w;
            }
            if (ii < deg2) {
                int m = sIdx[w][1][ii];
                float4 v = (MODE == 0)
                    ? *(const float4*)(Scol + (size_t)m * CC)
                    : __ldcg((const float4*)(Scol + (size_t)m * CC));
                acc2.x += v.x; acc2.y += v.y; acc2.z += v.z; acc2.w += v.w;
            }
        }
    } else {
        for (int w2 = 0; w2 < NN / 32; w2++) {
            unsigned int bits = Hrow1[w2];
            while (bits) {
                int q = __ffs(bits) - 1; bits &= bits - 1;
                int m = w2 * 32 + q;
                float4 v = (MODE == 0)
                    ? *(const float4*)(Scol + (size_t)m * CC)
                    : __ldcg((const float4*)(Scol + (size_t)m * CC));
                acc1.x += v.x; acc1.y += v.y; acc1.z += v.z; acc1.w += v.w;
            }
            bits = Hrow2[w2];
            while (bits) {
                int q = __ffs(bits) - 1; bits &= bits - 1;
                int m = w2 * 32 + q;
                float4 v = (MODE == 0)
                    ? *(const float4*)(Scol + (size_t)m * CC)
                    : __ldcg((const float4*)(Scol + (size_t)m * CC));
                acc2.x += v.x; acc2.y += v.y; acc2.z += v.z; acc2.w += v.w;
            }
        }
    }

    float inv1 = (deg1 > 0) ? (1.0f / (float)deg1) : 0.0f;
    float inv2 = (deg2 > 0) ? (1.0f / (float)deg2) : 0.0f;
    float4 vo1 = make_float4(acc1.x * inv1, acc1.y * inv1, acc1.z * inv1, acc1.w * inv1);
    float4 vo2 = make_float4(acc2.x * inv2, acc2.y * inv2, acc2.z * inv2, acc2.w * inv2);

    if (MODE == 0) {
        *(float4*)&g_E[((size_t)b * NN + n1) * CC + lane * 4] = vo1;
        *(float4*)&g_E[((size_t)b * NN + n2) * CC + lane * 4] = vo2;
    } else {
        const float* Yb = g_y + (size_t)b * NN * CC;
        float4 y1 = *(const float4*)(Yb + (size_t)n1 * CC + lane * 4);
        float4 y2 = *(const float4*)(Yb + (size_t)n2 * CC + lane * 4);
        float4 xe1 = make_float4(y1.x + vo1.x, y1.y + vo1.y, y1.z + vo1.z, y1.w + vo1.w);
        float4 xe2 = make_float4(y2.x + vo2.x, y2.y + vo2.y, y2.z + vo2.z, y2.w + vo2.w);
        *(float4*)&sXe[w][lane * 4] = xe1;                // local row = w
        *(float4*)&sXe[8 + w][lane * 4] = xe2;            // local row = 8 + w
        ps.x += xe1.x + xe2.x; ps.y += xe1.y + xe2.y;
        ps.z += xe1.z + xe2.z; ps.w += xe1.w + xe2.w;
        ps2.x += xe1.x * xe1.x + xe2.x * xe2.x;
        ps2.y += xe1.y * xe1.y + xe2.y * xe2.y;
        ps2.z += xe1.z * xe1.z + xe2.z * xe2.z;
        ps2.w += xe1.w * xe1.w + xe2.w * xe2.w;
    }
}

__global__ void __launch_bounds__(256, 4) tail_kernel(const float* __restrict__ gamma,
                                                      const float* __restrict__ beta,
                                                      float* __restrict__ out) {
    __shared__ unsigned short sIdx[8][2][512];   // 16 KB
    __shared__ float sXe[16][CC + 4];            // 8.25 KB
    __shared__ float sWPart[8][2][CC];           // 8 KB
    __shared__ float red[2][32];

    int bx = blockIdx.x;
    int tid = threadIdx.x;
    int b = bx >> 8;
    int n0 = (bx & 255) * 16;
    int w = tid >> 5, lane = tid & 31;

    // ---- compaction (ONCE, reused by both gather phases) ----
    int n1 = n0 + w, n2 = n0 + 8 + w;
    const unsigned int* Hrow1 = g_Hb + ((size_t)b * NN + n1) * (NN / 32);
    const unsigned int* Hrow2 = g_Hb + ((size_t)b * NN + n2) * (NN / 32);
    uint4 wv1 = ((const uint4*)Hrow1)[lane];
    uint4 wv2 = ((const uint4*)Hrow2)[lane];
    int cnt1 = __popc(wv1.x) + __popc(wv1.y) + __popc(wv1.z) + __popc(wv1.w);
    int cnt2 = __popc(wv2.x) + __popc(wv2.y) + __popc(wv2.z) + __popc(wv2.w);
    int pre1 = cnt1, pre2 = cnt2;
    #pragma unroll
    for (int o = 1; o < 32; o <<= 1) {
        int t1 = __shfl_up_sync(0xffffffffu, pre1, o);
        int t2 = __shfl_up_sync(0xffffffffu, pre2, o);
        if (lane >= o) { pre1 += t1; pre2 += t2; }
    }
    int deg1 = __shfl_sync(0xffffffffu, pre1, 31);
    int deg2 = __shfl_sync(0xffffffffu, pre2, 31);
    bool fast = (deg1 <= 512) && (deg2 <= 512);
    if (fast) {
        int kpos = pre1 - cnt1;
        unsigned int arr1[4] = {wv1.x, wv1.y, wv1.z, wv1.w};
        #pragma unroll
        for (int j = 0; j < 4; j++) {
            unsigned int bits = arr1[j];
            while (bits) {
                int q = __ffs(bits) - 1; bits &= bits - 1;
                sIdx[w][0][kpos++] = (unsigned short)(lane * 128 + j * 32 + q);
            }
        }
        kpos = pre2 - cnt2;
        unsigned int arr2[4] = {wv2.x, wv2.y, wv2.z, wv2.w};
        #pragma unroll
        for (int j = 0; j < 4; j++) {
            unsigned int bits = arr2[j];
            while (bits) {
                int q = __ffs(bits) - 1; bits &= bits - 1;
                sIdx[w][1][kpos++] = (unsigned short)(lane * 128 + j * 32 + q);
            }
        }
    }
    __syncwarp();

    float4 ps = make_float4(0.f, 0.f, 0.f, 0.f);
    float4 ps2 = make_float4(0.f, 0.f, 0.f, 0.f);

    // phase A: E = (H@y)/deg
    gather2<0>(b, n1, n2, deg1, deg2, fast, Hrow1, Hrow2, sIdx, sXe, w, lane, ps, ps2);
    grid_bar();
    // phase B: xe = y + (H@E)/deg  (smem only) + BN partials
    gather2<1>(b, n1, n2, deg1, deg2, fast, Hrow1, Hrow2, sIdx, sXe, w, lane, ps, ps2);
    {
        sWPart[w][0][lane * 4 + 0] = ps.x;  sWPart[w][0][lane * 4 + 1] = ps.y;
        sWPart[w][0][lane * 4 + 2] = ps.z;  sWPart[w][0][lane * 4 + 3] = ps.w;
        sWPart[w][1][lane * 4 + 0] = ps2.x; sWPart[w][1][lane * 4 + 1] = ps2.y;
        sWPart[w][1][lane * 4 + 2] = ps2.z; sWPart[w][1][lane * 4 + 3] = ps2.w;
        __syncthreads();
        int c = tid & 127, which = tid >> 7;
        float s = 0.f;
        #pragma unroll
        for (int k = 0; k < 8; k++) s += sWPart[k][which][c];
        g_partT[which][c][bx] = s;
    }
    grid_bar();
    // phase C: finalize stats (blocks 0..127 = channel)
    if (bx < CC) {
        int ch = bx;
        float s = 0.f, s2 = 0.f;
        #pragma unroll
        for (int k = 0; k < 2; k++) {
            int slot = tid + k * 256;
            s  += __ldcg(&g_partT[0][ch][slot]);
            s2 += __ldcg(&g_partT[1][ch][slot]);
        }
        #pragma unroll
        for (int o = 16; o > 0; o >>= 1) {
            s  += __shfl_xor_sync(0xffffffffu, s,  o);
            s2 += __shfl_xor_sync(0xffffffffu, s2, o);
        }
        if (lane == 0) { red[0][w] = s; red[1][w] = s2; }
        __syncthreads();
        if (tid == 0) {
            float ts = 0.f, ts2 = 0.f;
            #pragma unroll
            for (int k = 0; k < 8; k++) { ts += red[0][k]; ts2 += red[1][k]; }
            float mean = ts / (float)(BB * NN);
            float var = ts2 / (float)(BB * NN) - mean * mean;
            g_mean[ch] = mean;
            g_rstd[ch] = rsqrtf(var + BN_EPS);
        }
    }
    grid_bar();
    // phase D: BN + SiLU from smem xe -> NCHW output (16 n x 128 c)
    {
        int c = tid >> 1;                      // 0..127
        int half = tid & 1;                    // n-half: 0..7 or 8..15
        float mean = __ldcg(&g_mean[c]);
        float rstd = __ldcg(&g_rstd[c]);
        float ga = gamma[c], be = beta[c];
        float vout[8];
        #pragma unroll
        for (int k = 0; k < 8; k++) {
            float v = sXe[half * 8 + k][c];
            float xn = ga * ((v - mean) * rstd) + be;
            float sig = 1.0f / (1.0f + expf(-xn));
            vout[k] = xn * sig;
        }
        float* dst = out + ((size_t)b * CC + c) * NN + n0 + half * 8;
        *(float4*)dst       = make_float4(vout[0], vout[1], vout[2], vout[3]);
        *(float4*)(dst + 4) = make_float4(vout[4], vout[5], vout[6], vout[7]);
    }
}

// ---------------- entry ------------------------------------------------------
extern "C" void kernel_launch(void* const* d_in, const int* in_sizes, int n_in,
                              void* d_out, int out_size) {
    const float* x     = (const float*)d_in[0];
    const float* Wfc   = (const float*)d_in[1];
    const float* bfc   = (const float*)d_in[2];
    const float* gamma = (const float*)d_in[3];
    const float* beta  = (const float*)d_in[4];
    float* out = (float*)d_out;

    cudaFuncSetAttribute(gemm_fused, cudaFuncAttributeMaxDynamicSharedMemorySize, GM_SMEM);

    prep_kernel<<<dim3(NN / 32 + 1, 2, BB), 256>>>(x, Wfc);
    gemm_fused<<<dim3(592, BB), 256, GM_SMEM>>>(bfc);
    tail_kernel<<<TAIL_BLOCKS, 256>>>(gamma, beta, out);
}

// round 10
// speedup vs baseline: 2.0497x; 1.0871x over previous
#include <cuda_runtime.h>
#include <cuda_bf16.h>
#include <cstdint>

#define BB 2
#define CC 128
#define NN 4096
#define THRESH2 64.0f
#define BN_EPS 1e-5f

// ---------------- scratch (device globals) -----------------------------------
__device__ __nv_bfloat16 g_xb[BB * NN * CC];
__device__ __nv_bfloat16 g_xl[BB * NN * CC];
__device__ __nv_bfloat16 g_Whi[CC * CC];
__device__ __nv_bfloat16 g_Wlo[CC * CC];
__device__ float g_sqp[4][BB * NN];                   // per-channel-quarter sq partials
__device__ float g_y [BB * NN * CC];
__device__ unsigned int g_Hb[(size_t)BB * NN * (NN / 32)];
__device__ float g_partT[2][CC][512];
__device__ float g_mean[CC];
__device__ float g_rstd[CC];
__device__ unsigned int g_barcnt = 0;
__device__ unsigned int g_bargen = 0;

__device__ __forceinline__ uint32_t smem_u32(const void* p) {
    uint32_t a;
    asm("{ .reg .u64 t; cvta.to.shared.u64 t, %1; cvt.u32.u64 %0, t; }" : "=r"(a) : "l"(p));
    return a;
}
__device__ __forceinline__ void ldm_x4(uint32_t a[4], uint32_t addr) {
    asm volatile("ldmatrix.sync.aligned.m8n8.x4.shared.b16 {%0,%1,%2,%3}, [%4];"
                 : "=r"(a[0]), "=r"(a[1]), "=r"(a[2]), "=r"(a[3]) : "r"(addr));
}
__device__ __forceinline__ void mma16816(float c[4], const uint32_t a[4], const uint32_t b[2]) {
    asm volatile(
        "mma.sync.aligned.m16n8k16.row.col.f32.bf16.bf16.f32 "
        "{%0,%1,%2,%3}, {%4,%5,%6,%7}, {%8,%9}, {%0,%1,%2,%3};"
        : "+f"(c[0]), "+f"(c[1]), "+f"(c[2]), "+f"(c[3])
        : "r"(a[0]), "r"(a[1]), "r"(a[2]), "r"(a[3]), "r"(b[0]), "r"(b[1]));
}

// ---------------- K1: transpose + hi/lo split + sq quarters ------------------
// grid (129, 4, BB), block 128.  Tile = 32 n x 32 c.
__global__ void __launch_bounds__(128) prep_kernel(const float* __restrict__ x,
                                                   const float* __restrict__ Wfc) {
    int b = blockIdx.z;
    int cq = blockIdx.y;
    int tid = threadIdx.x;

    if (blockIdx.x == NN / 32) {               // W split: 8 blocks x 2048 elems
        int base = (b * 4 + cq) * 2048;
        #pragma unroll
        for (int k = 0; k < 16; k++) {
            int i = base + tid + k * 128;
            float v = Wfc[i];
            __nv_bfloat16 h = __float2bfloat16(v);
            g_Whi[i] = h;
            g_Wlo[i] = __float2bfloat16(v - __bfloat162float(h));
        }
        return;
    }

    __shared__ float tile[32][33];
    int n0 = blockIdx.x * 32;
    int c0 = cq * 32;
    {
        int c_local = tid >> 2, f = tid & 3;
        const float* src = x + ((size_t)b * CC + c0 + c_local) * NN + n0 + f * 8;
        float4 v0 = *(const float4*)src;
        float4 v1 = *(const float4*)(src + 4);
        tile[f * 8 + 0][c_local] = v0.x; tile[f * 8 + 1][c_local] = v0.y;
        tile[f * 8 + 2][c_local] = v0.z; tile[f * 8 + 3][c_local] = v0.w;
        tile[f * 8 + 4][c_local] = v1.x; tile[f * 8 + 5][c_local] = v1.y;
        tile[f * 8 + 6][c_local] = v1.z; tile[f * 8 + 7][c_local] = v1.w;
    }
    __syncthreads();

    int row = tid >> 2;
    int g = (tid & 3) * 8;
    float s = 0.f;
    uint32_t hw[4], lw[4];
    #pragma unroll
    for (int k = 0; k < 4; k++) {
        float v0 = tile[row][g + k * 2];
        float v1 = tile[row][g + k * 2 + 1];
        s += v0 * v0 + v1 * v1;
        __nv_bfloat16 h0 = __float2bfloat16(v0);
        __nv_bfloat16 h1 = __float2bfloat16(v1);
        __nv_bfloat16 l0 = __float2bfloat16(v0 - __bfloat162float(h0));
        __nv_bfloat16 l1 = __float2bfloat16(v1 - __bfloat162float(h1));
        hw[k] = (uint32_t)__bfloat16_as_ushort(h0) | ((uint32_t)__bfloat16_as_ushort(h1) << 16);
        lw[k] = (uint32_t)__bfloat16_as_ushort(l0) | ((uint32_t)__bfloat16_as_ushort(l1) << 16);
    }
    s += __shfl_xor_sync(0xffffffffu, s, 1);
    s += __shfl_xor_sync(0xffffffffu, s, 2);
    if ((tid & 3) == 0) g_sqp[cq][(size_t)b * NN + n0 + row] = s;

    size_t o = ((size_t)b * NN + n0 + row) * CC + c0 + g;
    *(uint4*)&g_xb[o] = make_uint4(hw[0], hw[1], hw[2], hw[3]);
    *(uint4*)&g_xl[o] = make_uint4(lw[0], lw[1], lw[2], lw[3]);
}

// ---------------- K2: fused gemm (H tiles + y tiles) -------------------------
#define HS_SQI 0
#define HS_SQJ 512
#define HS_A   1024
#define HS_B   33792
#define HS_H   66560
#define SH_STRIDE 144
#define YS_AH 0
#define YS_AL 16384
#define YS_WH 32768
#define YS_WL 65536
#define GM_SMEM 98304

__device__ void gemm_H_path(char* smem, int b, int tile_idx) {
    int tid = threadIdx.x;
    int wid = tid >> 5, lane = tid & 31;

    int idx = tile_idx, ti = 0, rem = 32;
    while (idx >= rem) { idx -= rem; ti++; rem--; }
    int tj = ti + idx;
    int n0 = ti * 128, m0 = tj * 128;

    float* sSqI = (float*)(smem + HS_SQI);
    float* sSqJ = (float*)(smem + HS_SQJ);
    if (tid < 128) {
        sSqI[tid] = g_sqp[0][(size_t)b * NN + n0 + tid] + g_sqp[1][(size_t)b * NN + n0 + tid]
                  + g_sqp[2][(size_t)b * NN + n0 + tid] + g_sqp[3][(size_t)b * NN + n0 + tid];
        sSqJ[tid] = g_sqp[0][(size_t)b * NN + m0 + tid] + g_sqp[1][(size_t)b * NN + m0 + tid]
                  + g_sqp[2][(size_t)b * NN + m0 + tid] + g_sqp[3][(size_t)b * NN + m0 + tid];
    }
    {
        const uint4* Ag = (const uint4*)(g_xb + ((size_t)b * NN + n0) * CC);
        const uint4* Bg = (const uint4*)(g_xb + ((size_t)b * NN + m0) * CC);
        #pragma unroll
        for (int it = 0; it < 8; it++) {
            int id = tid + it * 256;
            int row = id >> 4, ch = id & 15;
            int off = row * 256 + (ch ^ (row & 7)) * 16;
            *(uint4*)(smem + HS_A + off) = Ag[(size_t)row * 16 + ch];
            *(uint4*)(smem + HS_B + off) = Bg[(size_t)row * 16 + ch];
        }
    }
    __syncthreads();

    int warp_m = wid & 3, warp_n = wid >> 2;
    int mbase = warp_m * 32, nbase = warp_n * 64;

    float acc[2][8][4];
    #pragma unroll
    for (int mt = 0; mt < 2; mt++)
        #pragma unroll
        for (int nt = 0; nt < 8; nt++)
            #pragma unroll
            for (int q = 0; q < 4; q++) acc[mt][nt][q] = 0.f;

    uint32_t Abase = smem_u32(smem + HS_A);
    uint32_t Bbase = smem_u32(smem + HS_B);
    int a_row_local = lane & 15;
    int a_hi = lane >> 4;
    int bg = lane >> 3;
    int b_row_local = lane & 7;
    int b_nt_off = bg >> 1;
    int b_hi = bg & 1;

    #pragma unroll
    for (int kk = 0; kk < 8; kk++) {
        uint32_t afr[2][4];
        #pragma unroll
        for (int mt = 0; mt < 2; mt++) {
            int row = mbase + mt * 16 + a_row_local;
            int ch = (2 * kk + a_hi) ^ (row & 7);
            ldm_x4(afr[mt], Abase + row * 256 + ch * 16);
        }
        uint32_t bfr[8][2];
        #pragma unroll
        for (int nt2 = 0; nt2 < 4; nt2++) {
            int row = nbase + nt2 * 16 + b_nt_off * 8 + b_row_local;
            int ch = (2 * kk + b_hi) ^ (row & 7);
            uint32_t r4[4];
            ldm_x4(r4, Bbase + row * 256 + ch * 16);
            bfr[nt2 * 2][0] = r4[0]; bfr[nt2 * 2][1] = r4[1];
            bfr[nt2 * 2 + 1][0] = r4[2]; bfr[nt2 * 2 + 1][1] = r4[3];
        }
        #pragma unroll
        for (int mt = 0; mt < 2; mt++)
            #pragma unroll
            for (int nt = 0; nt < 8; nt++)
                mma16816(acc[mt][nt], afr[mt], bfr[nt]);
    }

    unsigned char* sH = (unsigned char*)(smem + HS_H);
    int rrow = lane >> 2;
    int ccol = (lane & 3) * 2;
    #pragma unroll
    for (int mt = 0; mt < 2; mt++) {
        #pragma unroll
        for (int nt = 0; nt < 8; nt++) {
            int col = nbase + nt * 8 + ccol;
            float sm0 = sSqJ[col], sm1 = sSqJ[col + 1];
            #pragma unroll
            for (int h = 0; h < 2; h++) {
                int row = mbase + mt * 16 + rrow + h * 8;
                float sqn = sSqI[row];
                float d20 = sqn + sm0 - 2.0f * acc[mt][nt][h * 2 + 0];
                float d21 = sqn + sm1 - 2.0f * acc[mt][nt][h * 2 + 1];
                sH[row * SH_STRIDE + col]     = (d20 < THRESH2) ? 1 : 0;
                sH[row * SH_STRIDE + col + 1] = (d21 < THRESH2) ? 1 : 0;
            }
        }
    }
    __syncthreads();

    unsigned int* Hb = g_Hb + (size_t)b * NN * (NN / 32);
    #pragma unroll
    for (int it = 0; it < 2; it++) {
        int id = tid + it * 256;
        int row = id >> 2, w = id & 3;
        const unsigned int* src = (const unsigned int*)(sH + row * SH_STRIDE + w * 32);
        unsigned int bits = 0;
        #pragma unroll
        for (int k = 0; k < 8; k++) {
            unsigned int u = src[k];
            bits |= (u & 1u) << (k * 4);
            bits |= ((u >> 8) & 1u) << (k * 4 + 1);
            bits |= ((u >> 16) & 1u) << (k * 4 + 2);
            bits |= ((u >> 24) & 1u) << (k * 4 + 3);
        }
        Hb[(size_t)(n0 + row) * (NN / 32) + (m0 >> 5) + w] = bits;
    }
    if (ti != tj && tid < 128) {
        int mrow = tid;
        unsigned int wbits[4];
        #pragma unroll
        for (int w = 0; w < 4; w++) {
            unsigned int bits = 0;
            #pragma unroll
            for (int q = 0; q < 32; q++)
                bits |= (unsigned int)(sH[(w * 32 + q) * SH_STRIDE + mrow] & 1u) << q;
            wbits[w] = bits;
        }
        *(uint4*)&Hb[(size_t)(m0 + mrow) * (NN / 32) + (n0 >> 5)] =
            make_uint4(wbits[0], wbits[1], wbits[2], wbits[3]);
    }
}

__device__ void gemm_y_path(char* smem, int b, int ytile, const float* __restrict__ bfc) {
    int tid = threadIdx.x;
    int wid = tid >> 5, lane = tid & 31;
    int n0 = ytile * 64;

    {
        const uint4* Ah = (const uint4*)(g_xb + ((size_t)b * NN + n0) * CC);
        const uint4* Al = (const uint4*)(g_xl + ((size_t)b * NN + n0) * CC);
        #pragma unroll
        for (int it = 0; it < 4; it++) {
            int id = tid + it * 256;
            int row = id >> 4, ch = id & 15;
            int off = row * 256 + (ch ^ (row & 7)) * 16;
            *(uint4*)(smem + YS_AH + off) = Ah[(size_t)row * 16 + ch];
            *(uint4*)(smem + YS_AL + off) = Al[(size_t)row * 16 + ch];
        }
        const uint4* Wh = (const uint4*)g_Whi;
        const uint4* Wl = (const uint4*)g_Wlo;
        #pragma unroll
        for (int it = 0; it < 8; it++) {
            int id = tid + it * 256;
            int row = id >> 4, ch = id & 15;
            int off = row * 256 + (ch ^ (row & 7)) * 16;
            *(uint4*)(smem + YS_WH + off) = Wh[(size_t)row * 16 + ch];
            *(uint4*)(smem + YS_WL + off) = Wl[(size_t)row * 16 + ch];
        }
    }
    __syncthreads();

    int warp_m = wid & 1, warp_n = wid >> 1;
    int mbase = warp_m * 32, nbase = warp_n * 32;

    float acc[2][4][4];
    #pragma unroll
    for (int mt = 0; mt < 2; mt++)
        #pragma unroll
        for (int nt = 0; nt < 4; nt++)
            #pragma unroll
            for (int q = 0; q < 4; q++) acc[mt][nt][q] = 0.f;

    int a_row_local = lane & 15;
    int a_hi = lane >> 4;
    int bg = lane >> 3;
    int b_row_local = lane & 7;
    int b_nt_off = bg >> 1;
    int b_hi = bg & 1;

    #pragma unroll
    for (int pass = 0; pass < 3; pass++) {
        uint32_t Abase = smem_u32(smem + (pass == 2 ? YS_AL : YS_AH));
        uint32_t Bbase = smem_u32(smem + (pass == 1 ? YS_WL : YS_WH));
        #pragma unroll
        for (int kk = 0; kk < 8; kk++) {
            uint32_t afr[2][4];
            #pragma unroll
            for (int mt = 0; mt < 2; mt++) {
                int row = mbase + mt * 16 + a_row_local;
                int ch = (2 * kk + a_hi) ^ (row & 7);
                ldm_x4(afr[mt], Abase + row * 256 + ch * 16);
            }
            uint32_t bfr[4][2];
            #pragma unroll
            for (int nt2 = 0; nt2 < 2; nt2++) {
                int row = nbase + nt2 * 16 + b_nt_off * 8 + b_row_local;
                int ch = (2 * kk + b_hi) ^ (row & 7);
                uint32_t r4[4];
                ldm_x4(r4, Bbase + row * 256 + ch * 16);
                bfr[nt2 * 2][0] = r4[0]; bfr[nt2 * 2][1] = r4[1];
                bfr[nt2 * 2 + 1][0] = r4[2]; bfr[nt2 * 2 + 1][1] = r4[3];
            }
            #pragma unroll
            for (int mt = 0; mt < 2; mt++)
                #pragma unroll
                for (int nt = 0; nt < 4; nt++)
                    mma16816(acc[mt][nt], afr[mt], bfr[nt]);
        }
    }

    int rrow = lane >> 2;
    int ccol = (lane & 3) * 2;
    float* Y = g_y + ((size_t)b * NN + n0) * CC;
    #pragma unroll
    for (int mt = 0; mt < 2; mt++) {
        #pragma unroll
        for (int nt = 0; nt < 4; nt++) {
            int col = nbase + nt * 8 + ccol;
            float b0 = bfc[col], b1 = bfc[col + 1];
            #pragma unroll
            for (int h = 0; h < 2; h++) {
                int row = mbase + mt * 16 + rrow + h * 8;
                Y[(size_t)row * CC + col]     = acc[mt][nt][h * 2 + 0] + b0;
                Y[(size_t)row * CC + col + 1] = acc[mt][nt][h * 2 + 1] + b1;
            }
        }
    }
}

__global__ void __launch_bounds__(256, 2) gemm_fused(const float* __restrict__ bfc) {
    extern __shared__ char smem[];
    int b = blockIdx.y;
    if (blockIdx.x < 528) gemm_H_path(smem, b, blockIdx.x);
    else                  gemm_y_path(smem, b, blockIdx.x - 528, bfc);
}

// ---------------- K3: mega tail (local two-hop aggregation) ------------------
#define TAIL_BLOCKS 512

__device__ __forceinline__ void grid_bar() {
    __syncthreads();
    if (threadIdx.x == 0) {
        __threadfence();
        unsigned int gen = *((volatile unsigned int*)&g_bargen);
        if (atomicAdd(&g_barcnt, 1u) == TAIL_BLOCKS - 1) {
            g_barcnt = 0;
            __threadfence();
            *((volatile unsigned int*)&g_bargen) = gen + 1;
        } else {
            while (*((volatile unsigned int*)&g_bargen) == gen) __nanosleep(64);
        }
    }
    __syncthreads();
}

// warp-collective: mean of y rows selected by maskrow (128 words).
// Returns float4 for this lane's 4 channels. scratch: 512-entry per-warp buffer.
__device__ float4 warp_gather_mean(const unsigned int* __restrict__ maskrow,
                                   unsigned short* scratch, int lane,
                                   const float* __restrict__ Ycol) {
    uint4 wv = ((const uint4*)maskrow)[lane];
    int cnt = __popc(wv.x) + __popc(wv.y) + __popc(wv.z) + __popc(wv.w);
    int pre = cnt;
    #pragma unroll
    for (int o = 1; o < 32; o <<= 1) {
        int t = __shfl_up_sync(0xffffffffu, pre, o);
        if (lane >= o) pre += t;
    }
    int deg = __shfl_sync(0xffffffffu, pre, 31);
    float4 acc = make_float4(0.f, 0.f, 0.f, 0.f);
    if (deg <= 512) {
        __syncwarp();
        int kpos = pre - cnt;
        unsigned int arr[4] = {wv.x, wv.y, wv.z, wv.w};
        #pragma unroll
        for (int j = 0; j < 4; j++) {
            unsigned int bits = arr[j];
            while (bits) {
                int q = __ffs(bits) - 1; bits &= bits - 1;
                scratch[kpos++] = (unsigned short)(lane * 128 + j * 32 + q);
            }
        }
        __syncwarp();
        for (int ii = 0; ii < deg; ii++) {
            int m = scratch[ii];
            float4 v = *(const float4*)(Ycol + (size_t)m * CC);
            acc.x += v.x; acc.y += v.y; acc.z += v.z; acc.w += v.w;
        }
    } else {
        for (int w2 = 0; w2 < NN / 32; w2++) {
            unsigned int bits = maskrow[w2];
            while (bits) {
                int q = __ffs(bits) - 1; bits &= bits - 1;
                int m = w2 * 32 + q;
                float4 v = *(const float4*)(Ycol + (size_t)m * CC);
                acc.x += v.x; acc.y += v.y; acc.z += v.z; acc.w += v.w;
            }
        }
    }
    float inv = (deg > 0) ? (1.0f / (float)deg) : 0.0f;
    return make_float4(acc.x * inv, acc.y * inv, acc.z * inv, acc.w * inv);
}

// x_out for row n with its compacted list (deg <= 512 case) or raw mask.
__device__ float4 compute_xout(int b, int n, const unsigned short* list, int deg,
                               const unsigned int* __restrict__ Hrow,
                               unsigned short* scratchB, int lane,
                               const float* __restrict__ Ycol) {
    const unsigned int* Hb = g_Hb + (size_t)b * NN * (NN / 32);
    float4 acc = make_float4(0.f, 0.f, 0.f, 0.f);
    if (deg <= 512) {
        for (int k = 0; k < deg; k++) {
            int m = list[k];
            float4 Em = warp_gather_mean(Hb + (size_t)m * (NN / 32), scratchB, lane, Ycol);
            acc.x += Em.x; acc.y += Em.y; acc.z += Em.z; acc.w += Em.w;
        }
    } else {
        for (int w2 = 0; w2 < NN / 32; w2++) {
            unsigned int bits = Hrow[w2];
            while (bits) {
                int q = __ffs(bits) - 1; bits &= bits - 1;
                int m = w2 * 32 + q;
                float4 Em = warp_gather_mean(Hb + (size_t)m * (NN / 32), scratchB, lane, Ycol);
                acc.x += Em.x; acc.y += Em.y; acc.z += Em.z; acc.w += Em.w;
            }
        }
    }
    float inv = (deg > 0) ? (1.0f / (float)deg) : 0.0f;
    return make_float4(acc.x * inv, acc.y * inv, acc.z * inv, acc.w * inv);
}

__global__ void __launch_bounds__(256, 4) tail_kernel(const float* __restrict__ gamma,
                                                      const float* __restrict__ beta,
                                                      float* __restrict__ out) {
    __shared__ unsigned short sIdxA[8][2][512];   // 16 KB
    __shared__ unsigned short sIdxB[8][512];      // 8 KB
    __shared__ float sXe[16][CC + 4];             // 8.25 KB
    __shared__ float sWPart[8][2][CC];            // 8 KB
    __shared__ float red[2][32];

    int bx = blockIdx.x;
    int tid = threadIdx.x;
    int b = bx >> 8;
    int n0 = (bx & 255) * 16;
    int w = tid >> 5, lane = tid & 31;

    const float* Yb = g_y + (size_t)b * NN * CC;
    const float* Ycol = Yb + lane * 4;

    int n1 = n0 + w, n2 = n0 + 8 + w;
    const unsigned int* Hrow1 = g_Hb + ((size_t)b * NN + n1) * (NN / 32);
    const unsigned int* Hrow2 = g_Hb + ((size_t)b * NN + n2) * (NN / 32);
    uint4 wv1 = ((const uint4*)Hrow1)[lane];
    uint4 wv2 = ((const uint4*)Hrow2)[lane];
    int cnt1 = __popc(wv1.x) + __popc(wv1.y) + __popc(wv1.z) + __popc(wv1.w);
    int cnt2 = __popc(wv2.x) + __popc(wv2.y) + __popc(wv2.z) + __popc(wv2.w);
    int pre1 = cnt1, pre2 = cnt2;
    #pragma unroll
    for (int o = 1; o < 32; o <<= 1) {
        int t1 = __shfl_up_sync(0xffffffffu, pre1, o);
        int t2 = __shfl_up_sync(0xffffffffu, pre2, o);
        if (lane >= o) { pre1 += t1; pre2 += t2; }
    }
    int deg1 = __shfl_sync(0xffffffffu, pre1, 31);
    int deg2 = __shfl_sync(0xffffffffu, pre2, 31);
    if (deg1 <= 512) {
        int kpos = pre1 - cnt1;
        unsigned int arr1[4] = {wv1.x, wv1.y, wv1.z, wv1.w};
        #pragma unroll
        for (int j = 0; j < 4; j++) {
            unsigned int bits = arr1[j];
            while (bits) {
                int q = __ffs(bits) - 1; bits &= bits - 1;
                sIdxA[w][0][kpos++] = (unsigned short)(lane * 128 + j * 32 + q);
            }
        }
    }
    if (deg2 <= 512) {
        int kpos = pre2 - cnt2;
        unsigned int arr2[4] = {wv2.x, wv2.y, wv2.z, wv2.w};
        #pragma unroll
        for (int j = 0; j < 4; j++) {
            unsigned int bits = arr2[j];
            while (bits) {
                int q = __ffs(bits) - 1; bits &= bits - 1;
                sIdxA[w][1][kpos++] = (unsigned short)(lane * 128 + j * 32 + q);
            }
        }
    }
    __syncwarp();

    // y rows (always needed)
    float4 y1 = *(const float4*)(Ycol + (size_t)n1 * CC);
    float4 y2 = *(const float4*)(Ycol + (size_t)n2 * CC);

    // x_out: fast path deg==1 -> mask = {self} -> x_out = y_n
    float4 xo1, xo2;
    if (deg1 == 1) { xo1 = y1; }
    else { xo1 = compute_xout(b, n1, sIdxA[w][0], deg1, Hrow1, sIdxB[w], lane, Ycol); }
    if (deg2 == 1) { xo2 = y2; }
    else { xo2 = compute_xout(b, n2, sIdxA[w][1], deg2, Hrow2, sIdxB[w], lane, Ycol); }

    float4 xe1 = make_float4(y1.x + xo1.x, y1.y + xo1.y, y1.z + xo1.z, y1.w + xo1.w);
    float4 xe2 = make_float4(y2.x + xo2.x, y2.y + xo2.y, y2.z + xo2.z, y2.w + xo2.w);
    *(float4*)&sXe[w][lane * 4]     = xe1;
    *(float4*)&sXe[8 + w][lane * 4] = xe2;

    // BN partials
    float4 ps = make_float4(xe1.x + xe2.x, xe1.y + xe2.y, xe1.z + xe2.z, xe1.w + xe2.w);
    float4 ps2 = make_float4(xe1.x * xe1.x + xe2.x * xe2.x,
                             xe1.y * xe1.y + xe2.y * xe2.y,
                             xe1.z * xe1.z + xe2.z * xe2.z,
                             xe1.w * xe1.w + xe2.w * xe2.w);
    {
        sWPart[w][0][lane * 4 + 0] = ps.x;  sWPart[w][0][lane * 4 + 1] = ps.y;
        sWPart[w][0][lane * 4 + 2] = ps.z;  sWPart[w][0][lane * 4 + 3] = ps.w;
        sWPart[w][1][lane * 4 + 0] = ps2.x; sWPart[w][1][lane * 4 + 1] = ps2.y;
        sWPart[w][1][lane * 4 + 2] = ps2.z; sWPart[w][1][lane * 4 + 3] = ps2.w;
        __syncthreads();
        int c = tid & 127, which = tid >> 7;
        float s = 0.f;
        #pragma unroll
        for (int k = 0; k < 8; k++) s += sWPart[k][which][c];
        g_partT[which][c][bx] = s;
    }
    grid_bar();
    // stats finalize (blocks 0..127 = channel)
    if (bx < CC) {
        int ch = bx;
        float s = 0.f, s2 = 0.f;
        #pragma unroll
        for (int k = 0; k < 2; k++) {
            int slot = tid + k * 256;
            s  += __ldcg(&g_partT[0][ch][slot]);
            s2 += __ldcg(&g_partT[1][ch][slot]);
        }
        #pragma unroll
        for (int o = 16; o > 0; o >>= 1) {
            s  += __shfl_xor_sync(0xffffffffu, s,  o);
            s2 += __shfl_xor_sync(0xffffffffu, s2, o);
        }
        if (lane == 0) { red[0][w] = s; red[1][w] = s2; }
        __syncthreads();
        if (tid == 0) {
            float ts = 0.f, ts2 = 0.f;
            #pragma unroll
            for (int k = 0; k < 8; k++) { ts += red[0][k]; ts2 += red[1][k]; }
            float mean = ts / (float)(BB * NN);
            float var = ts2 / (float)(BB * NN) - mean * mean;
            g_mean[ch] = mean;
            g_rstd[ch] = rsqrtf(var + BN_EPS);
        }
    }
    grid_bar();
    // BN + SiLU from smem xe -> NCHW output (16 n x 128 c)
    {
        int c = tid >> 1;
        int half = tid & 1;
        float mean = __ldcg(&g_mean[c]);
        float rstd = __ldcg(&g_rstd[c]);
        float ga = gamma[c], be = beta[c];
        float vout[8];
        #pragma unroll
        for (int k = 0; k < 8; k++) {
            float v = sXe[half * 8 + k][c];
            float xn = ga * ((v - mean) * rstd) + be;
            float sig = 1.0f / (1.0f + expf(-xn));
            vout[k] = xn * sig;
        }
        float* dst = out + ((size_t)b * CC + c) * NN + n0 + half * 8;
        *(float4*)dst       = make_float4(vout[0], vout[1], vout[2], vout[3]);
        *(float4*)(dst + 4) = make_float4(vout[4], vout[5], vout[6], vout[7]);
    }
}

// ---------------- entry ------------------------------------------------------
extern "C" void kernel_launch(void* const* d_in, const int* in_sizes, int n_in,
                              void* d_out, int out_size) {
    const float* x     = (const float*)d_in[0];
    const float* Wfc   = (const float*)d_in[1];
    const float* bfc   = (const float*)d_in[2];
    const float* gamma = (const float*)d_in[3];
    const float* beta  = (const float*)d_in[4];
    float* out = (float*)d_out;

    cudaFuncSetAttribute(gemm_fused, cudaFuncAttributeMaxDynamicSharedMemorySize, GM_SMEM);

    prep_kernel<<<dim3(NN / 32 + 1, 4, BB), 128>>>(x, Wfc);
    gemm_fused<<<dim3(592, BB), 256, GM_SMEM>>>(bfc);
    tail_kernel<<<TAIL_BLOCKS, 256>>>(gamma, beta, out);
}